// round 13
// baseline (speedup 1.0000x reference)
#include <cuda_runtime.h>
#include <cuda_bf16.h>
#include <cstdint>
#include <cstddef>

// Problem constants
#define Bb   8
#define Ll   1024
#define Dd   512
#define Hh   8
#define Qd   64
#define Mrows (Bb*Ll)          // 8192

// ---------------------------------------------------------------------------
// Scratch (no cudaMalloc allowed)
// ---------------------------------------------------------------------------
__device__ float g_Q [Mrows*Dd];
__device__ float g_Kt[Mrows*Dd];   // Kt[(b*512 + h*64 + d)*1024 + l]
__device__ float g_V [Mrows*Dd];
__device__ float g_mg[Mrows*Dd];   // merged[b,l, d*H + h]

__device__ __nv_bfloat16 g_xhi [Mrows*Dd];
__device__ __nv_bfloat16 g_xlo [Mrows*Dd];
__device__ __nv_bfloat16 g_xrhi[Mrows*Dd];
__device__ __nv_bfloat16 g_xrlo[Mrows*Dd];
__device__ __nv_bfloat16 g_mghi[Mrows*Dd];
__device__ __nv_bfloat16 g_mglo[Mrows*Dd];
__device__ __nv_bfloat16 g_whi [5*Dd*Dd];   // Wc,Wq,Wk,Wv,Wo
__device__ __nv_bfloat16 g_wlo [5*Dd*Dd];

// ---------------------------------------------------------------------------
// Warp MMA helpers (HMMA — available on plain sm_103)
// ---------------------------------------------------------------------------
__device__ __forceinline__ uint32_t smem_u32(const void* p) {
    uint32_t a;
    asm("{ .reg .u64 t; cvta.to.shared.u64 t, %1; cvt.u32.u64 %0, t; }" : "=r"(a) : "l"(p));
    return a;
}
__device__ __forceinline__ void ldsm_x4(uint32_t* r, uint32_t addr) {
    asm volatile("ldmatrix.sync.aligned.m8n8.x4.shared.b16 {%0,%1,%2,%3}, [%4];"
        : "=r"(r[0]), "=r"(r[1]), "=r"(r[2]), "=r"(r[3]) : "r"(addr));
}
__device__ __forceinline__ void mma16816(float* c, const uint32_t* a, const uint32_t* b) {
    asm volatile("mma.sync.aligned.m16n8k16.row.col.f32.bf16.bf16.f32 "
        "{%0,%1,%2,%3}, {%4,%5,%6,%7}, {%8,%9}, {%0,%1,%2,%3};"
        : "+f"(c[0]), "+f"(c[1]), "+f"(c[2]), "+f"(c[3])
        : "r"(a[0]), "r"(a[1]), "r"(a[2]), "r"(a[3]), "r"(b[0]), "r"(b[1]));
}

// ---------------------------------------------------------------------------
// fp32 -> bf16 hi/lo split
// ---------------------------------------------------------------------------
__global__ void cvt_split(const float* __restrict__ in,
                          __nv_bfloat16* __restrict__ hi,
                          __nv_bfloat16* __restrict__ lo, int n4)
{
    int i = blockIdx.x * blockDim.x + threadIdx.x;
    if (i >= n4) return;
    float4 v = reinterpret_cast<const float4*>(in)[i];
    __nv_bfloat16 h0 = __float2bfloat16(v.x);
    __nv_bfloat16 h1 = __float2bfloat16(v.y);
    __nv_bfloat16 h2 = __float2bfloat16(v.z);
    __nv_bfloat16 h3 = __float2bfloat16(v.w);
    __nv_bfloat162 ph0; ph0.x = h0; ph0.y = h1;
    __nv_bfloat162 ph1; ph1.x = h2; ph1.y = h3;
    __nv_bfloat162 pl0;
    pl0.x = __float2bfloat16(v.x - __bfloat162float(h0));
    pl0.y = __float2bfloat16(v.y - __bfloat162float(h1));
    __nv_bfloat162 pl1;
    pl1.x = __float2bfloat16(v.z - __bfloat162float(h2));
    pl1.y = __float2bfloat16(v.w - __bfloat162float(h3));
    reinterpret_cast<__nv_bfloat162*>(hi)[i*2]   = ph0;
    reinterpret_cast<__nv_bfloat162*>(hi)[i*2+1] = ph1;
    reinterpret_cast<__nv_bfloat162*>(lo)[i*2]   = pl0;
    reinterpret_cast<__nv_bfloat162*>(lo)[i*2+1] = pl1;
}

// ---------------------------------------------------------------------------
// HMMA split-precision GEMM: C[M,N] = (Ahi+Alo)[M,512] @ (Whi+Wlo)[N,512]^T + bias
// Tile 128x128, BK=32, 8 warps (2x4), warp tile 64x32, mma.m16n8k16.bf16.
// mode 0: C fp32 row-major.  mode 1: C transposed Kt layout.  mode 2: bf16 hi/lo.
// ---------------------------------------------------------------------------
#define LDT 40   // padded smem row stride (bf16 elems); 80B -> conflict-free LDSM

__global__ __launch_bounds__(256, 1)
void tg_gemm(const __nv_bfloat16* __restrict__ Ahi, const __nv_bfloat16* __restrict__ Alo,
             const __nv_bfloat16* __restrict__ Whi, const __nv_bfloat16* __restrict__ Wlo,
             const float* __restrict__ bias, float* __restrict__ C,
             __nv_bfloat16* __restrict__ Chi, __nv_bfloat16* __restrict__ Clo,
             int mode)
{
    __shared__ __nv_bfloat16 sAhi[128*LDT];
    __shared__ __nv_bfloat16 sAlo[128*LDT];
    __shared__ __nv_bfloat16 sWhi[128*LDT];
    __shared__ __nv_bfloat16 sWlo[128*LDT];

    const int tid  = threadIdx.x;
    const int wid  = tid >> 5;
    const int lane = tid & 31;
    const int bm   = blockIdx.x * 128;
    const int bn   = blockIdx.y * 128;

    const int wm = (wid >> 2) * 64;   // 0 or 64
    const int wn = (wid & 3) * 32;    // 0,32,64,96

    float acc[4][4][4];
#pragma unroll
    for (int i = 0; i < 4; i++)
#pragma unroll
        for (int j = 0; j < 4; j++)
#pragma unroll
            for (int k = 0; k < 4; k++) acc[i][j][k] = 0.0f;

    // ldmatrix source addresses (byte addresses in shared space)
    const uint32_t uAhi = smem_u32(sAhi);
    const uint32_t uAlo = smem_u32(sAlo);
    const uint32_t uWhi = smem_u32(sWhi);
    const uint32_t uWlo = smem_u32(sWlo);
    // A: row = wm + mf*16 + lane%16 ; col = kstep*16 + (lane>>4)*8
    const int a_row = wm + (lane & 15);
    const int a_colb = ((lane >> 4) * 8) * 2;
    // B: row = wn + p*16 + (lane>>4)*8 + lane%8 ; col = kstep*16 + ((lane>>3)&1)*8
    const int b_row = wn + ((lane >> 4) << 3) + (lane & 7);
    const int b_colb = (((lane >> 3) & 1) * 8) * 2;

    // gmem load indexing: 512 uint4 per tile, 2 per thread
    const int l_row0 = tid >> 1;            // 0..127
    const int l_c0   = (tid & 1) * 2;       // uint4 index 0 or 2 (we do c and c+1)

    for (int c = 0; c < 16; c++) {
        const int k0 = c * 32;
        // ---- load 4 tiles [128 x 32 bf16] ----
#pragma unroll
        for (int cc = 0; cc < 2; cc++) {
            int c16 = l_c0 + cc;                 // 0..3 (8 bf16 each)
            size_t ga = (size_t)(bm + l_row0) * 512 + k0 + c16 * 8;
            size_t gw = (size_t)(bn + l_row0) * 512 + k0 + c16 * 8;
            int so = l_row0 * LDT + c16 * 8;
            *reinterpret_cast<uint4*>(&sAhi[so]) = *reinterpret_cast<const uint4*>(Ahi + ga);
            *reinterpret_cast<uint4*>(&sAlo[so]) = *reinterpret_cast<const uint4*>(Alo + ga);
            *reinterpret_cast<uint4*>(&sWhi[so]) = *reinterpret_cast<const uint4*>(Whi + gw);
            *reinterpret_cast<uint4*>(&sWlo[so]) = *reinterpret_cast<const uint4*>(Wlo + gw);
        }
        __syncthreads();

#pragma unroll
        for (int ks = 0; ks < 2; ks++) {
            const int kb = ks * 16 * 2;      // byte offset of k-step
            uint32_t af[4][4];
            uint32_t bh[2][4], bl[2][4];
            // A_hi fragments
#pragma unroll
            for (int mf = 0; mf < 4; mf++)
                ldsm_x4(af[mf], uAhi + (uint32_t)((a_row + mf * 16) * LDT * 2) + kb + a_colb);
            // B_hi / B_lo fragments (p covers n16 each)
#pragma unroll
            for (int p = 0; p < 2; p++) {
                uint32_t off = (uint32_t)((b_row + p * 16) * LDT * 2) + kb + b_colb;
                ldsm_x4(bh[p], uWhi + off);
                ldsm_x4(bl[p], uWlo + off);
            }
            // pass hi*hi and hi*lo
#pragma unroll
            for (int mf = 0; mf < 4; mf++)
#pragma unroll
                for (int nf = 0; nf < 4; nf++) {
                    mma16816(acc[mf][nf], af[mf], &bh[nf >> 1][(nf & 1) * 2]);
                    mma16816(acc[mf][nf], af[mf], &bl[nf >> 1][(nf & 1) * 2]);
                }
            // A_lo fragments (overwrite)
#pragma unroll
            for (int mf = 0; mf < 4; mf++)
                ldsm_x4(af[mf], uAlo + (uint32_t)((a_row + mf * 16) * LDT * 2) + kb + a_colb);
            // pass lo*hi
#pragma unroll
            for (int mf = 0; mf < 4; mf++)
#pragma unroll
                for (int nf = 0; nf < 4; nf++)
                    mma16816(acc[mf][nf], af[mf], &bh[nf >> 1][(nf & 1) * 2]);
        }
        __syncthreads();
    }

    // ---- epilogue ----
    const int gid = lane >> 2;
    const int tq  = lane & 3;
#pragma unroll
    for (int mf = 0; mf < 4; mf++) {
#pragma unroll
        for (int nf = 0; nf < 4; nf++) {
            const float* a = acc[mf][nf];
            int m0 = bm + wm + mf * 16 + gid;
            int n0 = bn + wn + nf * 8 + tq * 2;
            float b0 = __ldg(&bias[n0]);
            float b1 = __ldg(&bias[n0 + 1]);
            if (mode == 0) {
                float2 v0 = make_float2(a[0] + b0, a[1] + b1);
                float2 v1 = make_float2(a[2] + b0, a[3] + b1);
                *reinterpret_cast<float2*>(&C[(size_t)m0 * 512 + n0])       = v0;
                *reinterpret_cast<float2*>(&C[(size_t)(m0 + 8) * 512 + n0]) = v1;
            } else if (mode == 1) {
                int bi0 = m0 >> 10, l0v = m0 & 1023;
                int m1 = m0 + 8;
                int bi1 = m1 >> 10, l1v = m1 & 1023;
                C[((size_t)(bi0 * 512 + n0    )) * 1024 + l0v] = a[0] + b0;
                C[((size_t)(bi0 * 512 + n0 + 1)) * 1024 + l0v] = a[1] + b1;
                C[((size_t)(bi1 * 512 + n0    )) * 1024 + l1v] = a[2] + b0;
                C[((size_t)(bi1 * 512 + n0 + 1)) * 1024 + l1v] = a[3] + b1;
            } else {
                float v0 = a[0] + b0, v1 = a[1] + b1;
                float v2 = a[2] + b0, v3 = a[3] + b1;
                __nv_bfloat162 ph0, pl0, ph1, pl1;
                ph0.x = __float2bfloat16(v0); ph0.y = __float2bfloat16(v1);
                pl0.x = __float2bfloat16(v0 - __bfloat162float(ph0.x));
                pl0.y = __float2bfloat16(v1 - __bfloat162float(ph0.y));
                ph1.x = __float2bfloat16(v2); ph1.y = __float2bfloat16(v3);
                pl1.x = __float2bfloat16(v2 - __bfloat162float(ph1.x));
                pl1.y = __float2bfloat16(v3 - __bfloat162float(ph1.y));
                *reinterpret_cast<__nv_bfloat162*>(&Chi[(size_t)m0 * 512 + n0])       = ph0;
                *reinterpret_cast<__nv_bfloat162*>(&Clo[(size_t)m0 * 512 + n0])       = pl0;
                *reinterpret_cast<__nv_bfloat162*>(&Chi[(size_t)(m0 + 8) * 512 + n0]) = ph1;
                *reinterpret_cast<__nv_bfloat162*>(&Clo[(size_t)(m0 + 8) * 512 + n0]) = pl1;
            }
        }
    }
}

// ---------------------------------------------------------------------------
// Fused attention (unchanged from passing R9 kernel)
// ---------------------------------------------------------------------------
#define SROW 1032
#define ATTN_SMEM_FLOATS (32*SROW + 64*36 + 256*68)
#define ATTN_SMEM_BYTES  (ATTN_SMEM_FLOATS * 4)

__global__ __launch_bounds__(256)
void attn_k(const float* __restrict__ Q, const float* __restrict__ Kt,
            const float* __restrict__ V, float* __restrict__ scores,
            float* __restrict__ merged)
{
    extern __shared__ float sm[];
    float* S   = sm;
    float* Qst = S + 32 * SROW;
    float* KV  = Qst + 64 * 36;

    const int tid = threadIdx.x;
    const int qt  = blockIdx.x;
    const int h   = blockIdx.y;
    const int b   = blockIdx.z;
    const int l0  = qt * 32;

    {
        const float* Qg = Q + ((size_t)(b * 1024 + l0)) * 512 + h * 64;
#pragma unroll
        for (int i = 0; i < 2; i++) {
            int idx = tid + i * 256;
            int r   = idx >> 4;
            int d4  = (idx & 15) << 2;
            float4 v = *reinterpret_cast<const float4*>(&Qg[(size_t)r * 512 + d4]);
            Qst[(d4 + 0) * 36 + r] = v.x * 0.125f;
            Qst[(d4 + 1) * 36 + r] = v.y * 0.125f;
            Qst[(d4 + 2) * 36 + r] = v.z * 0.125f;
            Qst[(d4 + 3) * 36 + r] = v.w * 0.125f;
        }
    }

    const int lane = tid & 31;
    const int w    = tid >> 5;

    {
        const int c0 = lane * 8;
        const int r0 = w * 4;
        for (int jt = 0; jt < 4; jt++) {
            __syncthreads();
            const float* Kg = Kt + ((size_t)(b * 512 + h * 64)) * 1024 + jt * 256;
#pragma unroll
            for (int i = 0; i < 16; i++) {
                int idx = tid + i * 256;
                int d   = idx >> 6;
                int c4  = (idx & 63) << 2;
                float4 v = *reinterpret_cast<const float4*>(&Kg[(size_t)d * 1024 + c4]);
                *reinterpret_cast<float4*>(&KV[d * 260 + c4]) = v;
            }
            __syncthreads();

            float acc[4][8];
#pragma unroll
            for (int i = 0; i < 4; i++)
#pragma unroll
                for (int j = 0; j < 8; j++) acc[i][j] = 0.0f;

#pragma unroll 8
            for (int d = 0; d < 64; d++) {
                float4 aq = *reinterpret_cast<const float4*>(&Qst[d * 36 + r0]);
                float4 b0 = *reinterpret_cast<const float4*>(&KV[d * 260 + c0]);
                float4 b1 = *reinterpret_cast<const float4*>(&KV[d * 260 + c0 + 4]);
                float av[4] = {aq.x, aq.y, aq.z, aq.w};
                float bv[8] = {b0.x, b0.y, b0.z, b0.w, b1.x, b1.y, b1.z, b1.w};
#pragma unroll
                for (int i = 0; i < 4; i++)
#pragma unroll
                    for (int j = 0; j < 8; j++)
                        acc[i][j] = fmaf(av[i], bv[j], acc[i][j]);
            }

#pragma unroll
            for (int i = 0; i < 4; i++) {
                float* srow = &S[(size_t)(r0 + i) * SROW + jt * 256 + c0];
                *reinterpret_cast<float4*>(srow)     = make_float4(acc[i][0], acc[i][1], acc[i][2], acc[i][3]);
                *reinterpret_cast<float4*>(srow + 4) = make_float4(acc[i][4], acc[i][5], acc[i][6], acc[i][7]);
            }
        }
        __syncthreads();
    }

    {
        for (int rr = 0; rr < 4; rr++) {
            int r = w * 4 + rr;
            float* row = &S[(size_t)r * SROW];
            float mx = -1e30f;
            for (int j = lane; j < 1024; j += 32) mx = fmaxf(mx, row[j]);
#pragma unroll
            for (int o = 16; o; o >>= 1) mx = fmaxf(mx, __shfl_xor_sync(0xffffffffu, mx, o));
            float s = 0.0f;
            for (int j = lane; j < 1024; j += 32) {
                float e = __expf(row[j] - mx);
                row[j] = e;
                s += e;
            }
#pragma unroll
            for (int o = 16; o; o >>= 1) s += __shfl_xor_sync(0xffffffffu, s, o);
            float inv = 1.0f / s;
            float* sg = scores + (((size_t)(b * 8 + h)) * 1024 + (l0 + r)) * 1024;
            for (int j = lane; j < 1024; j += 32) {
                float p = row[j] * inv;
                row[j] = p;
                sg[j]  = p;
            }
        }
    }

    {
        const int tx  = tid & 15;
        const int tyv = tid >> 4;
        const int d0  = tx * 4;
        const int r0  = tyv * 2;
        float o[2][4];
#pragma unroll
        for (int i = 0; i < 2; i++)
#pragma unroll
            for (int j = 0; j < 4; j++) o[i][j] = 0.0f;

        for (int jt = 0; jt < 4; jt++) {
            __syncthreads();
            const float* Vg = V + ((size_t)(b * 1024 + jt * 256)) * 512 + h * 64;
#pragma unroll
            for (int i = 0; i < 16; i++) {
                int idx = tid + i * 256;
                int jr  = idx >> 4;
                int d4  = (idx & 15) << 2;
                float4 v = *reinterpret_cast<const float4*>(&Vg[(size_t)jr * 512 + d4]);
                *reinterpret_cast<float4*>(&KV[jr * 68 + d4]) = v;
            }
            __syncthreads();

#pragma unroll 8
            for (int jj = 0; jj < 256; jj++) {
                float4 bv = *reinterpret_cast<const float4*>(&KV[jj * 68 + d0]);
                float a0 = S[(size_t)(r0 + 0) * SROW + jt * 256 + jj];
                float a1 = S[(size_t)(r0 + 1) * SROW + jt * 256 + jj];
                o[0][0] = fmaf(a0, bv.x, o[0][0]);
                o[0][1] = fmaf(a0, bv.y, o[0][1]);
                o[0][2] = fmaf(a0, bv.z, o[0][2]);
                o[0][3] = fmaf(a0, bv.w, o[0][3]);
                o[1][0] = fmaf(a1, bv.x, o[1][0]);
                o[1][1] = fmaf(a1, bv.y, o[1][1]);
                o[1][2] = fmaf(a1, bv.z, o[1][2]);
                o[1][3] = fmaf(a1, bv.w, o[1][3]);
            }
        }

        float* mg = merged + ((size_t)(b * 1024 + l0)) * 512 + h;
#pragma unroll
        for (int i = 0; i < 2; i++)
#pragma unroll
            for (int jd = 0; jd < 4; jd++)
                mg[(size_t)(r0 + i) * 512 + (size_t)(d0 + jd) * 8] = o[i][jd];
    }
}

// ---------------------------------------------------------------------------
// Launch
// ---------------------------------------------------------------------------
extern "C" void kernel_launch(void* const* d_in, const int* in_sizes, int n_in,
                              void* d_out, int out_size)
{
    const float* x  = (const float*)d_in[0];
    const float* Wc = (const float*)d_in[1];
    const float* bc = (const float*)d_in[2];
    const float* Wq = (const float*)d_in[3];
    const float* bq = (const float*)d_in[4];
    const float* Wk = (const float*)d_in[5];
    const float* bk = (const float*)d_in[6];
    const float* Wv = (const float*)d_in[7];
    const float* bv = (const float*)d_in[8];
    const float* Wo = (const float*)d_in[9];
    const float* bo = (const float*)d_in[10];

    float* out    = (float*)d_out;
    float* scores = out + (size_t)Bb * Ll * Dd;

    float *Qb, *Ktb, *Vb, *mg;
    cudaGetSymbolAddress((void**)&Qb,  g_Q);
    cudaGetSymbolAddress((void**)&Ktb, g_Kt);
    cudaGetSymbolAddress((void**)&Vb,  g_V);
    cudaGetSymbolAddress((void**)&mg,  g_mg);

    __nv_bfloat16 *xhi, *xlo, *xrhi, *xrlo, *mghi, *mglo, *whi, *wlo;
    cudaGetSymbolAddress((void**)&xhi,  g_xhi);
    cudaGetSymbolAddress((void**)&xlo,  g_xlo);
    cudaGetSymbolAddress((void**)&xrhi, g_xrhi);
    cudaGetSymbolAddress((void**)&xrlo, g_xrlo);
    cudaGetSymbolAddress((void**)&mghi, g_mghi);
    cudaGetSymbolAddress((void**)&mglo, g_mglo);
    cudaGetSymbolAddress((void**)&whi,  g_whi);
    cudaGetSymbolAddress((void**)&wlo,  g_wlo);

    cudaFuncSetAttribute((const void*)attn_k,
                         cudaFuncAttributeMaxDynamicSharedMemorySize, ATTN_SMEM_BYTES);

    const int WN = Dd * Dd;           // 262144 elems per weight
    cvt_split<<<(Mrows*Dd/4 + 255)/256, 256>>>(x,  xhi, xlo, Mrows*Dd/4);
    cvt_split<<<(WN/4 + 255)/256, 256>>>(Wc, whi + 0*WN, wlo + 0*WN, WN/4);
    cvt_split<<<(WN/4 + 255)/256, 256>>>(Wq, whi + 1*WN, wlo + 1*WN, WN/4);
    cvt_split<<<(WN/4 + 255)/256, 256>>>(Wk, whi + 2*WN, wlo + 2*WN, WN/4);
    cvt_split<<<(WN/4 + 255)/256, 256>>>(Wv, whi + 3*WN, wlo + 3*WN, WN/4);
    cvt_split<<<(WN/4 + 255)/256, 256>>>(Wo, whi + 4*WN, wlo + 4*WN, WN/4);

    dim3 gg(Mrows / 128, Dd / 128);   // (64, 4)

    // x_r = x @ Wc^T + bc  (split bf16 output)
    tg_gemm<<<gg, 256>>>(xhi, xlo, whi + 0*WN, wlo + 0*WN, bc,
                         nullptr, xrhi, xrlo, 2);
    // Q = x @ Wq^T + bq
    tg_gemm<<<gg, 256>>>(xhi, xlo, whi + 1*WN, wlo + 1*WN, bq,
                         Qb, nullptr, nullptr, 0);
    // K = x_r @ Wk^T + bk  (transposed Kt output)
    tg_gemm<<<gg, 256>>>(xrhi, xrlo, whi + 2*WN, wlo + 2*WN, bk,
                         Ktb, nullptr, nullptr, 1);
    // V = x_r @ Wv^T + bv
    tg_gemm<<<gg, 256>>>(xrhi, xrlo, whi + 3*WN, wlo + 3*WN, bv,
                         Vb, nullptr, nullptr, 0);

    attn_k<<<dim3(32, Hh, Bb), 256, ATTN_SMEM_BYTES>>>(Qb, Ktb, Vb, scores, mg);

    cvt_split<<<(Mrows*Dd/4 + 255)/256, 256>>>(mg, mghi, mglo, Mrows*Dd/4);
    // out = merged @ Wo^T + bo
    tg_gemm<<<gg, 256>>>(mghi, mglo, whi + 4*WN, wlo + 4*WN, bo,
                         out, nullptr, nullptr, 0);
}

// round 14
// speedup vs baseline: 1.4525x; 1.4525x over previous
#include <cuda_runtime.h>
#include <cuda_bf16.h>
#include <cstdint>
#include <cstddef>

// Problem constants
#define Bb   8
#define Ll   1024
#define Dd   512
#define Hh   8
#define Qd   64
#define Mrows (Bb*Ll)          // 8192

// ---------------------------------------------------------------------------
// Scratch (no cudaMalloc allowed)
// ---------------------------------------------------------------------------
__device__ __nv_bfloat16 g_xhi [Mrows*Dd];
__device__ __nv_bfloat16 g_xlo [Mrows*Dd];
__device__ __nv_bfloat16 g_xrhi[Mrows*Dd];
__device__ __nv_bfloat16 g_xrlo[Mrows*Dd];
__device__ __nv_bfloat16 g_Qhi [Mrows*Dd];
__device__ __nv_bfloat16 g_Qlo [Mrows*Dd];
__device__ __nv_bfloat16 g_Khi [Mrows*Dd];
__device__ __nv_bfloat16 g_Klo [Mrows*Dd];
__device__ __nv_bfloat16 g_Vthi[Mrows*Dd];  // Vt[(b*512 + h*64 + d)*1024 + l]
__device__ __nv_bfloat16 g_Vtlo[Mrows*Dd];
__device__ __nv_bfloat16 g_mghi[Mrows*Dd];  // merged[b,l, d*H + h]
__device__ __nv_bfloat16 g_mglo[Mrows*Dd];
__device__ __nv_bfloat16 g_whi [5*Dd*Dd];   // Wc,Wq,Wk,Wv,Wo
__device__ __nv_bfloat16 g_wlo [5*Dd*Dd];

// ---------------------------------------------------------------------------
// Warp MMA helpers (HMMA — available on plain sm_103)
// ---------------------------------------------------------------------------
__device__ __forceinline__ uint32_t smem_u32(const void* p) {
    uint32_t a;
    asm("{ .reg .u64 t; cvta.to.shared.u64 t, %1; cvt.u32.u64 %0, t; }" : "=r"(a) : "l"(p));
    return a;
}
__device__ __forceinline__ void ldsm_x4(uint32_t* r, uint32_t addr) {
    asm volatile("ldmatrix.sync.aligned.m8n8.x4.shared.b16 {%0,%1,%2,%3}, [%4];"
        : "=r"(r[0]), "=r"(r[1]), "=r"(r[2]), "=r"(r[3]) : "r"(addr));
}
__device__ __forceinline__ void ldsm_x2(uint32_t* r, uint32_t addr) {
    asm volatile("ldmatrix.sync.aligned.m8n8.x2.shared.b16 {%0,%1}, [%2];"
        : "=r"(r[0]), "=r"(r[1]) : "r"(addr));
}
__device__ __forceinline__ void mma16816(float* c, const uint32_t* a, const uint32_t* b) {
    asm volatile("mma.sync.aligned.m16n8k16.row.col.f32.bf16.bf16.f32 "
        "{%0,%1,%2,%3}, {%4,%5,%6,%7}, {%8,%9}, {%0,%1,%2,%3};"
        : "+f"(c[0]), "+f"(c[1]), "+f"(c[2]), "+f"(c[3])
        : "r"(a[0]), "r"(a[1]), "r"(a[2]), "r"(a[3]), "r"(b[0]), "r"(b[1]));
}

// ---------------------------------------------------------------------------
// fp32 -> bf16 hi/lo split
// ---------------------------------------------------------------------------
__global__ void cvt_split(const float* __restrict__ in,
                          __nv_bfloat16* __restrict__ hi,
                          __nv_bfloat16* __restrict__ lo, int n4)
{
    int i = blockIdx.x * blockDim.x + threadIdx.x;
    if (i >= n4) return;
    float4 v = reinterpret_cast<const float4*>(in)[i];
    __nv_bfloat16 h0 = __float2bfloat16(v.x);
    __nv_bfloat16 h1 = __float2bfloat16(v.y);
    __nv_bfloat16 h2 = __float2bfloat16(v.z);
    __nv_bfloat16 h3 = __float2bfloat16(v.w);
    __nv_bfloat162 ph0; ph0.x = h0; ph0.y = h1;
    __nv_bfloat162 ph1; ph1.x = h2; ph1.y = h3;
    __nv_bfloat162 pl0;
    pl0.x = __float2bfloat16(v.x - __bfloat162float(h0));
    pl0.y = __float2bfloat16(v.y - __bfloat162float(h1));
    __nv_bfloat162 pl1;
    pl1.x = __float2bfloat16(v.z - __bfloat162float(h2));
    pl1.y = __float2bfloat16(v.w - __bfloat162float(h3));
    reinterpret_cast<__nv_bfloat162*>(hi)[i*2]   = ph0;
    reinterpret_cast<__nv_bfloat162*>(hi)[i*2+1] = ph1;
    reinterpret_cast<__nv_bfloat162*>(lo)[i*2]   = pl0;
    reinterpret_cast<__nv_bfloat162*>(lo)[i*2+1] = pl1;
}

// ---------------------------------------------------------------------------
// HMMA split-precision GEMM: C[M,N] = (Ahi+Alo)[M,512] @ (Whi+Wlo)[N,512]^T + bias
// Tile 128x128, BK=32, 8 warps (2x4), warp tile 64x32, mma.m16n8k16.bf16.
// mode 0: C fp32 row-major.  mode 2: bf16 hi/lo row-major.
// mode 3: bf16 hi/lo transposed Vt layout [(bidx*512 + n)*1024 + l].
// ---------------------------------------------------------------------------
#define LDT 40   // padded smem row stride (bf16 elems); 80B -> conflict-free LDSM

__global__ __launch_bounds__(256, 1)
void tg_gemm(const __nv_bfloat16* __restrict__ Ahi, const __nv_bfloat16* __restrict__ Alo,
             const __nv_bfloat16* __restrict__ Whi, const __nv_bfloat16* __restrict__ Wlo,
             const float* __restrict__ bias, float* __restrict__ C,
             __nv_bfloat16* __restrict__ Chi, __nv_bfloat16* __restrict__ Clo,
             int mode)
{
    __shared__ __nv_bfloat16 sAhi[128*LDT];
    __shared__ __nv_bfloat16 sAlo[128*LDT];
    __shared__ __nv_bfloat16 sWhi[128*LDT];
    __shared__ __nv_bfloat16 sWlo[128*LDT];

    const int tid  = threadIdx.x;
    const int wid  = tid >> 5;
    const int lane = tid & 31;
    const int bm   = blockIdx.x * 128;
    const int bn   = blockIdx.y * 128;

    const int wm = (wid >> 2) * 64;   // 0 or 64
    const int wn = (wid & 3) * 32;    // 0,32,64,96

    float acc[4][4][4];
#pragma unroll
    for (int i = 0; i < 4; i++)
#pragma unroll
        for (int j = 0; j < 4; j++)
#pragma unroll
            for (int k = 0; k < 4; k++) acc[i][j][k] = 0.0f;

    const uint32_t uAhi = smem_u32(sAhi);
    const uint32_t uAlo = smem_u32(sAlo);
    const uint32_t uWhi = smem_u32(sWhi);
    const uint32_t uWlo = smem_u32(sWlo);
    const int a_row = wm + (lane & 15);
    const int a_colb = ((lane >> 4) * 8) * 2;
    const int b_row = wn + ((lane >> 4) << 3) + (lane & 7);
    const int b_colb = (((lane >> 3) & 1) * 8) * 2;

    const int l_row0 = tid >> 1;            // 0..127
    const int l_c0   = (tid & 1) * 2;       // uint4 index 0 or 2

    for (int c = 0; c < 16; c++) {
        const int k0 = c * 32;
#pragma unroll
        for (int cc = 0; cc < 2; cc++) {
            int c16 = l_c0 + cc;
            size_t ga = (size_t)(bm + l_row0) * 512 + k0 + c16 * 8;
            size_t gw = (size_t)(bn + l_row0) * 512 + k0 + c16 * 8;
            int so = l_row0 * LDT + c16 * 8;
            *reinterpret_cast<uint4*>(&sAhi[so]) = *reinterpret_cast<const uint4*>(Ahi + ga);
            *reinterpret_cast<uint4*>(&sAlo[so]) = *reinterpret_cast<const uint4*>(Alo + ga);
            *reinterpret_cast<uint4*>(&sWhi[so]) = *reinterpret_cast<const uint4*>(Whi + gw);
            *reinterpret_cast<uint4*>(&sWlo[so]) = *reinterpret_cast<const uint4*>(Wlo + gw);
        }
        __syncthreads();

#pragma unroll
        for (int ks = 0; ks < 2; ks++) {
            const int kb = ks * 16 * 2;
            uint32_t af[4][4];
            uint32_t bh[2][4], bl[2][4];
#pragma unroll
            for (int mf = 0; mf < 4; mf++)
                ldsm_x4(af[mf], uAhi + (uint32_t)((a_row + mf * 16) * LDT * 2) + kb + a_colb);
#pragma unroll
            for (int p = 0; p < 2; p++) {
                uint32_t off = (uint32_t)((b_row + p * 16) * LDT * 2) + kb + b_colb;
                ldsm_x4(bh[p], uWhi + off);
                ldsm_x4(bl[p], uWlo + off);
            }
#pragma unroll
            for (int mf = 0; mf < 4; mf++)
#pragma unroll
                for (int nf = 0; nf < 4; nf++) {
                    mma16816(acc[mf][nf], af[mf], &bh[nf >> 1][(nf & 1) * 2]);
                    mma16816(acc[mf][nf], af[mf], &bl[nf >> 1][(nf & 1) * 2]);
                }
#pragma unroll
            for (int mf = 0; mf < 4; mf++)
                ldsm_x4(af[mf], uAlo + (uint32_t)((a_row + mf * 16) * LDT * 2) + kb + a_colb);
#pragma unroll
            for (int mf = 0; mf < 4; mf++)
#pragma unroll
                for (int nf = 0; nf < 4; nf++)
                    mma16816(acc[mf][nf], af[mf], &bh[nf >> 1][(nf & 1) * 2]);
        }
        __syncthreads();
    }

    // ---- epilogue ----
    const int gid = lane >> 2;
    const int tq  = lane & 3;
#pragma unroll
    for (int mf = 0; mf < 4; mf++) {
#pragma unroll
        for (int nf = 0; nf < 4; nf++) {
            const float* a = acc[mf][nf];
            int m0 = bm + wm + mf * 16 + gid;
            int n0 = bn + wn + nf * 8 + tq * 2;
            float b0 = __ldg(&bias[n0]);
            float b1 = __ldg(&bias[n0 + 1]);
            float v0 = a[0] + b0, v1 = a[1] + b1;
            float v2 = a[2] + b0, v3 = a[3] + b1;
            if (mode == 0) {
                *reinterpret_cast<float2*>(&C[(size_t)m0 * 512 + n0])       = make_float2(v0, v1);
                *reinterpret_cast<float2*>(&C[(size_t)(m0 + 8) * 512 + n0]) = make_float2(v2, v3);
            } else if (mode == 2) {
                __nv_bfloat162 ph0, pl0, ph1, pl1;
                ph0.x = __float2bfloat16(v0); ph0.y = __float2bfloat16(v1);
                pl0.x = __float2bfloat16(v0 - __bfloat162float(ph0.x));
                pl0.y = __float2bfloat16(v1 - __bfloat162float(ph0.y));
                ph1.x = __float2bfloat16(v2); ph1.y = __float2bfloat16(v3);
                pl1.x = __float2bfloat16(v2 - __bfloat162float(ph1.x));
                pl1.y = __float2bfloat16(v3 - __bfloat162float(ph1.y));
                *reinterpret_cast<__nv_bfloat162*>(&Chi[(size_t)m0 * 512 + n0])       = ph0;
                *reinterpret_cast<__nv_bfloat162*>(&Clo[(size_t)m0 * 512 + n0])       = pl0;
                *reinterpret_cast<__nv_bfloat162*>(&Chi[(size_t)(m0 + 8) * 512 + n0]) = ph1;
                *reinterpret_cast<__nv_bfloat162*>(&Clo[(size_t)(m0 + 8) * 512 + n0]) = pl1;
            } else {
                // mode 3: transposed split  Vt[(bidx*512 + n)*1024 + l]
                int bi0 = m0 >> 10, l0v = m0 & 1023;
                int m1 = m0 + 8;
                int bi1 = m1 >> 10, l1v = m1 & 1023;
                __nv_bfloat16 h;
                h = __float2bfloat16(v0);
                Chi[((size_t)(bi0*512 + n0    ))*1024 + l0v] = h;
                Clo[((size_t)(bi0*512 + n0    ))*1024 + l0v] = __float2bfloat16(v0 - __bfloat162float(h));
                h = __float2bfloat16(v1);
                Chi[((size_t)(bi0*512 + n0 + 1))*1024 + l0v] = h;
                Clo[((size_t)(bi0*512 + n0 + 1))*1024 + l0v] = __float2bfloat16(v1 - __bfloat162float(h));
                h = __float2bfloat16(v2);
                Chi[((size_t)(bi1*512 + n0    ))*1024 + l1v] = h;
                Clo[((size_t)(bi1*512 + n0    ))*1024 + l1v] = __float2bfloat16(v2 - __bfloat162float(h));
                h = __float2bfloat16(v3);
                Chi[((size_t)(bi1*512 + n0 + 1))*1024 + l1v] = h;
                Clo[((size_t)(bi1*512 + n0 + 1))*1024 + l1v] = __float2bfloat16(v3 - __bfloat162float(h));
            }
        }
    }
}

// ---------------------------------------------------------------------------
// Fused attention with HMMA split-precision QK^T and PV.
// CTA = (b, h, 32 q rows); 8 warps; S tile 32x1024 fp32 in smem; scores
// written exactly once; merged written as split bf16.
// ---------------------------------------------------------------------------
#define SROW 1032
// smem byte offsets
#define AOFF_QHI  132096                       // after S (32*1032*4)
#define AOFF_QLO  (AOFF_QHI + 4608)            // 32*72*2
#define AOFF_KHI  (AOFF_QLO + 4608)            // 141312
#define AOFF_KLO  (AOFF_KHI + 18432)           // 128*72*2
#define AOFF_VHI  AOFF_KHI                     // V aliases K region
#define AOFF_VLO  (AOFF_VHI + 17408)           // 64*136*2
#define AOFF_PHI  (AOFF_KLO + 18432)           // 178176
#define AOFF_PLO  (AOFF_PHI + 8704)            // 32*136*2
#define ATTN_SMEM_BYTES (AOFF_PLO + 8704)      // 195584

__global__ __launch_bounds__(256, 1)
void attn_mma(const __nv_bfloat16* __restrict__ Qhi, const __nv_bfloat16* __restrict__ Qlo,
              const __nv_bfloat16* __restrict__ Khi, const __nv_bfloat16* __restrict__ Klo,
              const __nv_bfloat16* __restrict__ Vthi, const __nv_bfloat16* __restrict__ Vtlo,
              float* __restrict__ scores,
              __nv_bfloat16* __restrict__ mghi, __nv_bfloat16* __restrict__ mglo)
{
    extern __shared__ char smc[];
    float* S = reinterpret_cast<float*>(smc);
    __nv_bfloat16* sQh = reinterpret_cast<__nv_bfloat16*>(smc + AOFF_QHI);
    __nv_bfloat16* sQl = reinterpret_cast<__nv_bfloat16*>(smc + AOFF_QLO);
    __nv_bfloat16* sKh = reinterpret_cast<__nv_bfloat16*>(smc + AOFF_KHI);
    __nv_bfloat16* sKl = reinterpret_cast<__nv_bfloat16*>(smc + AOFF_KLO);
    __nv_bfloat16* sVh = reinterpret_cast<__nv_bfloat16*>(smc + AOFF_VHI);
    __nv_bfloat16* sVl = reinterpret_cast<__nv_bfloat16*>(smc + AOFF_VLO);
    __nv_bfloat16* sPh = reinterpret_cast<__nv_bfloat16*>(smc + AOFF_PHI);
    __nv_bfloat16* sPl = reinterpret_cast<__nv_bfloat16*>(smc + AOFF_PLO);

    const int tid  = threadIdx.x;
    const int lane = tid & 31;
    const int w    = tid >> 5;
    const int qt   = blockIdx.x;
    const int h    = blockIdx.y;
    const int b    = blockIdx.z;
    const int l0   = qt * 32;

    // ---- load Q tile 32x64 hi/lo (stride 72) ----
    {
        int r = tid >> 3, c = tid & 7;
        size_t g = ((size_t)(b * 1024 + l0 + r)) * 512 + h * 64 + c * 8;
        *reinterpret_cast<uint4*>(&sQh[r * 72 + c * 8]) = *reinterpret_cast<const uint4*>(&Qhi[g]);
        *reinterpret_cast<uint4*>(&sQl[r * 72 + c * 8]) = *reinterpret_cast<const uint4*>(&Qlo[g]);
    }
    __syncthreads();

    const uint32_t uQh = smem_u32(sQh), uQl = smem_u32(sQl);
    const uint32_t uKh = smem_u32(sKh), uKl = smem_u32(sKl);
    const uint32_t uVh = smem_u32(sVh), uVl = smem_u32(sVl);
    const uint32_t uPh = smem_u32(sPh), uPl = smem_u32(sPl);

    const int a_row  = lane & 15;
    const int a_colb = (lane >> 4) * 16;               // bytes
    const int gid = lane >> 2;
    const int tq  = lane & 3;

    // hoist Q fragments: [mf][kk][4]
    uint32_t qh[2][4][4], ql[2][4][4];
#pragma unroll
    for (int mf = 0; mf < 2; mf++)
#pragma unroll
        for (int kk = 0; kk < 4; kk++) {
            uint32_t off = (uint32_t)((mf * 16 + a_row) * 144) + kk * 32 + a_colb;
            ldsm_x4(qh[mf][kk], uQh + off);
            ldsm_x4(ql[mf][kk], uQl + off);
        }

    // ---- S phase: 8 chunks of 128 tokens ----
    {
        const int wn = w * 16;                         // warp col slice within chunk
        const int b_row  = wn + ((lane >> 4) << 3) + (lane & 7);
        const int b_colb = ((lane >> 3) & 1) * 16;
        for (int jt = 0; jt < 8; jt++) {
            __syncthreads();
#pragma unroll
            for (int i = 0; i < 4; i++) {
                int idx = tid + i * 256;               // 0..1023
                int r = idx >> 3, c = idx & 7;
                size_t g = ((size_t)(b * 1024 + jt * 128 + r)) * 512 + h * 64 + c * 8;
                *reinterpret_cast<uint4*>(&sKh[r * 72 + c * 8]) = *reinterpret_cast<const uint4*>(&Khi[g]);
                *reinterpret_cast<uint4*>(&sKl[r * 72 + c * 8]) = *reinterpret_cast<const uint4*>(&Klo[g]);
            }
            __syncthreads();

            float acc[2][2][4];
#pragma unroll
            for (int i = 0; i < 2; i++)
#pragma unroll
                for (int j = 0; j < 2; j++)
#pragma unroll
                    for (int k = 0; k < 4; k++) acc[i][j][k] = 0.0f;

#pragma unroll
            for (int kk = 0; kk < 4; kk++) {
                uint32_t bhf[4], blf[4];
                uint32_t off = (uint32_t)(b_row * 144) + kk * 32 + b_colb;
                ldsm_x4(bhf, uKh + off);
                ldsm_x4(blf, uKl + off);
#pragma unroll
                for (int mf = 0; mf < 2; mf++)
#pragma unroll
                    for (int nf = 0; nf < 2; nf++) {
                        mma16816(acc[mf][nf], qh[mf][kk], &bhf[nf * 2]);
                        mma16816(acc[mf][nf], qh[mf][kk], &blf[nf * 2]);
                        mma16816(acc[mf][nf], ql[mf][kk], &bhf[nf * 2]);
                    }
            }
            // write S (scaled by exact 0.125)
#pragma unroll
            for (int mf = 0; mf < 2; mf++)
#pragma unroll
                for (int nf = 0; nf < 2; nf++) {
                    int row = mf * 16 + gid;
                    int col = jt * 128 + wn + nf * 8 + tq * 2;
                    const float* a = acc[mf][nf];
                    *reinterpret_cast<float2*>(&S[(size_t)row * SROW + col]) =
                        make_float2(a[0] * 0.125f, a[1] * 0.125f);
                    *reinterpret_cast<float2*>(&S[(size_t)(row + 8) * SROW + col]) =
                        make_float2(a[2] * 0.125f, a[3] * 0.125f);
                }
        }
        __syncthreads();
    }

    // ---- softmax per row; write scores once ----
    {
        for (int rr = 0; rr < 4; rr++) {
            int r = w * 4 + rr;
            float* row = &S[(size_t)r * SROW];
            float mx = -1e30f;
            for (int j = lane; j < 1024; j += 32) mx = fmaxf(mx, row[j]);
#pragma unroll
            for (int o = 16; o; o >>= 1) mx = fmaxf(mx, __shfl_xor_sync(0xffffffffu, mx, o));
            float s = 0.0f;
            for (int j = lane; j < 1024; j += 32) {
                float e = __expf(row[j] - mx);
                row[j] = e;
                s += e;
            }
#pragma unroll
            for (int o = 16; o; o >>= 1) s += __shfl_xor_sync(0xffffffffu, s, o);
            float inv = 1.0f / s;
            float* sg = scores + (((size_t)(b * 8 + h)) * 1024 + (l0 + r)) * 1024;
            for (int j = lane; j < 1024; j += 32) {
                float p = row[j] * inv;
                row[j] = p;
                sg[j]  = p;
            }
        }
    }

    // ---- PV phase: 8 chunks of 128 tokens, split P and V ----
    {
        const int d0 = w * 8;                          // warp dim slice
        float oacc[2][4];
#pragma unroll
        for (int i = 0; i < 2; i++)
#pragma unroll
            for (int j = 0; j < 4; j++) oacc[i][j] = 0.0f;

        const int v_rowb = (d0 + (lane & 7)) * 272;    // byte row offset into Vt smem
        const int v_colb = ((lane >> 3) & 1) * 16;

        for (int jt = 0; jt < 8; jt++) {
            __syncthreads();
            // convert P chunk 32x128 -> Phi/Plo (stride 136)
#pragma unroll
            for (int i = 0; i < 8; i++) {
                int idx = tid + i * 256;               // 0..2047 pairs
                int r = idx >> 6, c = (idx & 63) * 2;
                float2 v = *reinterpret_cast<const float2*>(&S[(size_t)r * SROW + jt * 128 + c]);
                __nv_bfloat162 ph, pl;
                ph.x = __float2bfloat16(v.x);
                ph.y = __float2bfloat16(v.y);
                pl.x = __float2bfloat16(v.x - __bfloat162float(ph.x));
                pl.y = __float2bfloat16(v.y - __bfloat162float(ph.y));
                *reinterpret_cast<__nv_bfloat162*>(&sPh[r * 136 + c]) = ph;
                *reinterpret_cast<__nv_bfloat162*>(&sPl[r * 136 + c]) = pl;
            }
            // load Vt chunk 64 dims x 128 tokens (stride 136)
#pragma unroll
            for (int i = 0; i < 4; i++) {
                int idx = tid + i * 256;               // 0..1023
                int r = idx >> 4, c = idx & 15;
                size_t g = ((size_t)(b * 512 + h * 64 + r)) * 1024 + jt * 128 + c * 8;
                *reinterpret_cast<uint4*>(&sVh[r * 136 + c * 8]) = *reinterpret_cast<const uint4*>(&Vthi[g]);
                *reinterpret_cast<uint4*>(&sVl[r * 136 + c * 8]) = *reinterpret_cast<const uint4*>(&Vtlo[g]);
            }
            __syncthreads();

#pragma unroll
            for (int kk = 0; kk < 8; kk++) {
                uint32_t bh2[2], bl2[2];
                uint32_t voff = (uint32_t)v_rowb + kk * 32 + v_colb;
                ldsm_x2(bh2, uVh + voff);
                ldsm_x2(bl2, uVl + voff);
#pragma unroll
                for (int mf = 0; mf < 2; mf++) {
                    uint32_t ah[4], al[4];
                    uint32_t aoff = (uint32_t)((mf * 16 + a_row) * 272) + kk * 32 + a_colb;
                    ldsm_x4(ah, uPh + aoff);
                    ldsm_x4(al, uPl + aoff);
                    mma16816(oacc[mf], ah, bh2);
                    mma16816(oacc[mf], ah, bl2);
                    mma16816(oacc[mf], al, bh2);
                }
            }
        }

        // epilogue: merged[b, l, d*H + h] as split bf16
#pragma unroll
        for (int mf = 0; mf < 2; mf++) {
            int r0v = mf * 16 + gid;
            int d   = d0 + tq * 2;
            const float* a = oacc[mf];
            size_t base0 = ((size_t)(b * 1024 + l0 + r0v)) * 512 + h;
            size_t base1 = ((size_t)(b * 1024 + l0 + r0v + 8)) * 512 + h;
            __nv_bfloat16 hh;
            hh = __float2bfloat16(a[0]);
            mghi[base0 + (size_t)d * 8]       = hh;
            mglo[base0 + (size_t)d * 8]       = __float2bfloat16(a[0] - __bfloat162float(hh));
            hh = __float2bfloat16(a[1]);
            mghi[base0 + (size_t)(d + 1) * 8] = hh;
            mglo[base0 + (size_t)(d + 1) * 8] = __float2bfloat16(a[1] - __bfloat162float(hh));
            hh = __float2bfloat16(a[2]);
            mghi[base1 + (size_t)d * 8]       = hh;
            mglo[base1 + (size_t)d * 8]       = __float2bfloat16(a[2] - __bfloat162float(hh));
            hh = __float2bfloat16(a[3]);
            mghi[base1 + (size_t)(d + 1) * 8] = hh;
            mglo[base1 + (size_t)(d + 1) * 8] = __float2bfloat16(a[3] - __bfloat162float(hh));
        }
    }
}

// ---------------------------------------------------------------------------
// Launch
// ---------------------------------------------------------------------------
extern "C" void kernel_launch(void* const* d_in, const int* in_sizes, int n_in,
                              void* d_out, int out_size)
{
    const float* x  = (const float*)d_in[0];
    const float* Wc = (const float*)d_in[1];
    const float* bc = (const float*)d_in[2];
    const float* Wq = (const float*)d_in[3];
    const float* bq = (const float*)d_in[4];
    const float* Wk = (const float*)d_in[5];
    const float* bk = (const float*)d_in[6];
    const float* Wv = (const float*)d_in[7];
    const float* bv = (const float*)d_in[8];
    const float* Wo = (const float*)d_in[9];
    const float* bo = (const float*)d_in[10];

    float* out    = (float*)d_out;
    float* scores = out + (size_t)Bb * Ll * Dd;

    __nv_bfloat16 *xhi, *xlo, *xrhi, *xrlo, *qhi, *qlo, *khi, *klo,
                  *vthi, *vtlo, *mghi, *mglo, *whi, *wlo;
    cudaGetSymbolAddress((void**)&xhi,  g_xhi);
    cudaGetSymbolAddress((void**)&xlo,  g_xlo);
    cudaGetSymbolAddress((void**)&xrhi, g_xrhi);
    cudaGetSymbolAddress((void**)&xrlo, g_xrlo);
    cudaGetSymbolAddress((void**)&qhi,  g_Qhi);
    cudaGetSymbolAddress((void**)&qlo,  g_Qlo);
    cudaGetSymbolAddress((void**)&khi,  g_Khi);
    cudaGetSymbolAddress((void**)&klo,  g_Klo);
    cudaGetSymbolAddress((void**)&vthi, g_Vthi);
    cudaGetSymbolAddress((void**)&vtlo, g_Vtlo);
    cudaGetSymbolAddress((void**)&mghi, g_mghi);
    cudaGetSymbolAddress((void**)&mglo, g_mglo);
    cudaGetSymbolAddress((void**)&whi,  g_whi);
    cudaGetSymbolAddress((void**)&wlo,  g_wlo);

    cudaFuncSetAttribute((const void*)attn_mma,
                         cudaFuncAttributeMaxDynamicSharedMemorySize, ATTN_SMEM_BYTES);

    const int WN = Dd * Dd;           // 262144 elems per weight
    cvt_split<<<(Mrows*Dd/4 + 255)/256, 256>>>(x,  xhi, xlo, Mrows*Dd/4);
    cvt_split<<<(WN/4 + 255)/256, 256>>>(Wc, whi + 0*WN, wlo + 0*WN, WN/4);
    cvt_split<<<(WN/4 + 255)/256, 256>>>(Wq, whi + 1*WN, wlo + 1*WN, WN/4);
    cvt_split<<<(WN/4 + 255)/256, 256>>>(Wk, whi + 2*WN, wlo + 2*WN, WN/4);
    cvt_split<<<(WN/4 + 255)/256, 256>>>(Wv, whi + 3*WN, wlo + 3*WN, WN/4);
    cvt_split<<<(WN/4 + 255)/256, 256>>>(Wo, whi + 4*WN, wlo + 4*WN, WN/4);

    dim3 gg(Mrows / 128, Dd / 128);   // (64, 4)

    // x_r = x @ Wc^T + bc  (split bf16 row-major)
    tg_gemm<<<gg, 256>>>(xhi, xlo, whi + 0*WN, wlo + 0*WN, bc,
                         nullptr, xrhi, xrlo, 2);
    // Q = x @ Wq^T + bq    (split bf16 row-major)
    tg_gemm<<<gg, 256>>>(xhi, xlo, whi + 1*WN, wlo + 1*WN, bq,
                         nullptr, qhi, qlo, 2);
    // K = x_r @ Wk^T + bk  (split bf16 row-major)
    tg_gemm<<<gg, 256>>>(xrhi, xrlo, whi + 2*WN, wlo + 2*WN, bk,
                         nullptr, khi, klo, 2);
    // V = x_r @ Wv^T + bv  (split bf16 transposed Vt)
    tg_gemm<<<gg, 256>>>(xrhi, xrlo, whi + 3*WN, wlo + 3*WN, bv,
                         nullptr, vthi, vtlo, 3);

    attn_mma<<<dim3(32, Hh, Bb), 256, ATTN_SMEM_BYTES>>>(
        qhi, qlo, khi, klo, vthi, vtlo, scores, mghi, mglo);

    // out = merged @ Wo^T + bo  (fp32)
    tg_gemm<<<gg, 256>>>(mghi, mglo, whi + 4*WN, wlo + 4*WN, bo,
                         out, nullptr, nullptr, 0);
}

// round 15
// speedup vs baseline: 1.8051x; 1.2428x over previous
#include <cuda_runtime.h>
#include <cuda_bf16.h>
#include <cstdint>
#include <cstddef>

// Problem constants
#define Bb   8
#define Ll   1024
#define Dd   512
#define Hh   8
#define Qd   64
#define Mrows (Bb*Ll)          // 8192

// ---------------------------------------------------------------------------
// Scratch (no cudaMalloc allowed)
// ---------------------------------------------------------------------------
__device__ __nv_bfloat16 g_xhi [Mrows*Dd];
__device__ __nv_bfloat16 g_xlo [Mrows*Dd];
__device__ __nv_bfloat16 g_xrhi[Mrows*Dd];
__device__ __nv_bfloat16 g_xrlo[Mrows*Dd];
__device__ __nv_bfloat16 g_Qhi [Mrows*Dd];
__device__ __nv_bfloat16 g_Qlo [Mrows*Dd];
__device__ __nv_bfloat16 g_Khi [Mrows*Dd];
__device__ __nv_bfloat16 g_Klo [Mrows*Dd];
__device__ __nv_bfloat16 g_Vthi[Mrows*Dd];  // Vt[(b*512 + h*64 + d)*1024 + l]
__device__ __nv_bfloat16 g_Vtlo[Mrows*Dd];
__device__ __nv_bfloat16 g_mghi[Mrows*Dd];  // merged[b,l, d*H + h]
__device__ __nv_bfloat16 g_mglo[Mrows*Dd];
__device__ __nv_bfloat16 g_whi [5*Dd*Dd];   // Wc,Wq,Wk,Wv,Wo
__device__ __nv_bfloat16 g_wlo [5*Dd*Dd];

// ---------------------------------------------------------------------------
// PTX helpers
// ---------------------------------------------------------------------------
__device__ __forceinline__ uint32_t smem_u32(const void* p) {
    uint32_t a;
    asm("{ .reg .u64 t; cvta.to.shared.u64 t, %1; cvt.u32.u64 %0, t; }" : "=r"(a) : "l"(p));
    return a;
}
__device__ __forceinline__ void ldsm_x4(uint32_t* r, uint32_t addr) {
    asm volatile("ldmatrix.sync.aligned.m8n8.x4.shared.b16 {%0,%1,%2,%3}, [%4];"
        : "=r"(r[0]), "=r"(r[1]), "=r"(r[2]), "=r"(r[3]) : "r"(addr));
}
__device__ __forceinline__ void ldsm_x2(uint32_t* r, uint32_t addr) {
    asm volatile("ldmatrix.sync.aligned.m8n8.x2.shared.b16 {%0,%1}, [%2];"
        : "=r"(r[0]), "=r"(r[1]) : "r"(addr));
}
__device__ __forceinline__ void mma16816(float* c, const uint32_t* a, const uint32_t* b) {
    asm volatile("mma.sync.aligned.m16n8k16.row.col.f32.bf16.bf16.f32 "
        "{%0,%1,%2,%3}, {%4,%5,%6,%7}, {%8,%9}, {%0,%1,%2,%3};"
        : "+f"(c[0]), "+f"(c[1]), "+f"(c[2]), "+f"(c[3])
        : "r"(a[0]), "r"(a[1]), "r"(a[2]), "r"(a[3]), "r"(b[0]), "r"(b[1]));
}
__device__ __forceinline__ void cp_async16(uint32_t s, const void* g) {
    asm volatile("cp.async.cg.shared.global [%0], [%1], 16;" :: "r"(s), "l"(g));
}
__device__ __forceinline__ void cp_commit() { asm volatile("cp.async.commit_group;" ::: "memory"); }
__device__ __forceinline__ void cp_wait1()  { asm volatile("cp.async.wait_group 1;" ::: "memory"); }
__device__ __forceinline__ void cp_wait0()  { asm volatile("cp.async.wait_group 0;" ::: "memory"); }

// ---------------------------------------------------------------------------
// fp32 -> bf16 hi/lo split
// ---------------------------------------------------------------------------
__device__ __forceinline__ void split_store(float vx, float vy,
                                            __nv_bfloat16* hi, __nv_bfloat16* lo, size_t idx)
{
    __nv_bfloat162 ph, pl;
    ph.x = __float2bfloat16(vx); ph.y = __float2bfloat16(vy);
    pl.x = __float2bfloat16(vx - __bfloat162float(ph.x));
    pl.y = __float2bfloat16(vy - __bfloat162float(ph.y));
    *reinterpret_cast<__nv_bfloat162*>(hi + idx) = ph;
    *reinterpret_cast<__nv_bfloat162*>(lo + idx) = pl;
}

__global__ void cvt_split(const float* __restrict__ in,
                          __nv_bfloat16* __restrict__ hi,
                          __nv_bfloat16* __restrict__ lo, int n4)
{
    int i = blockIdx.x * blockDim.x + threadIdx.x;
    if (i >= n4) return;
    float4 v = reinterpret_cast<const float4*>(in)[i];
    split_store(v.x, v.y, hi, lo, (size_t)i * 4);
    split_store(v.z, v.w, hi, lo, (size_t)i * 4 + 2);
}

// 5 weight matrices in one launch (grid.y selects segment)
__global__ void cvt_split5(const float* __restrict__ w0, const float* __restrict__ w1,
                           const float* __restrict__ w2, const float* __restrict__ w3,
                           const float* __restrict__ w4,
                           __nv_bfloat16* __restrict__ hi, __nv_bfloat16* __restrict__ lo)
{
    const int seg = blockIdx.y;
    const float* in = (seg == 0) ? w0 : (seg == 1) ? w1 : (seg == 2) ? w2 : (seg == 3) ? w3 : w4;
    hi += (size_t)seg * Dd * Dd;
    lo += (size_t)seg * Dd * Dd;
    int i = blockIdx.x * blockDim.x + threadIdx.x;   // n4 = Dd*Dd/4 = 65536
    float4 v = reinterpret_cast<const float4*>(in)[i];
    split_store(v.x, v.y, hi, lo, (size_t)i * 4);
    split_store(v.z, v.w, hi, lo, (size_t)i * 4 + 2);
}

// ---------------------------------------------------------------------------
// HMMA split-precision GEMM, cp.async double-buffered.
// C[M,N] = (Ahi+Alo)[M,512] @ (Whi+Wlo)[N,512]^T + bias
// Tile 128x128, BK=32, 8 warps (2x4), warp tile 64x32, mma.m16n8k16.bf16.
// mode 0: C fp32 row-major.  mode 2: bf16 hi/lo row-major.
// mode 3: bf16 hi/lo transposed Vt layout [(bidx*512 + n)*1024 + l].
// ---------------------------------------------------------------------------
#define LDTB 80         // smem row stride in BYTES (40 bf16) -> conflict-free LDSM
#define GSTG 40960      // bytes per pipeline stage (4 tiles x 128 x 80B)
#define GM_SMEM (2*GSTG)

__global__ __launch_bounds__(256, 2)
void tg_gemm(const __nv_bfloat16* __restrict__ Ahi, const __nv_bfloat16* __restrict__ Alo,
             const __nv_bfloat16* __restrict__ Whi, const __nv_bfloat16* __restrict__ Wlo,
             const float* __restrict__ bias, float* __restrict__ C,
             __nv_bfloat16* __restrict__ Chi, __nv_bfloat16* __restrict__ Clo,
             int mode)
{
    extern __shared__ char gsm[];
    const uint32_t sb0 = smem_u32(gsm);

    const int tid  = threadIdx.x;
    const int wid  = tid >> 5;
    const int lane = tid & 31;
    const int bm   = blockIdx.x * 128;
    const int bn   = blockIdx.y * 128;
    const int wm = (wid >> 2) * 64;
    const int wn = (wid & 3) * 32;

    float acc[4][4][4];
#pragma unroll
    for (int i = 0; i < 4; i++)
#pragma unroll
        for (int j = 0; j < 4; j++)
#pragma unroll
            for (int k = 0; k < 4; k++) acc[i][j][k] = 0.0f;

    const int a_row  = wm + (lane & 15);
    const int a_colb = (lane >> 4) * 16;
    const int b_row  = wn + ((lane >> 4) << 3) + (lane & 7);
    const int b_colb = ((lane >> 3) & 1) * 16;

    const int l_row0 = tid >> 1;            // 0..127
    const int l_c0   = (tid & 1) * 2;       // 16B-unit index 0 or 2

#define GM_LOAD(cch, stg) do {                                                  \
        uint32_t _sb = sb0 + (stg) * GSTG;                                      \
        _Pragma("unroll")                                                       \
        for (int cc = 0; cc < 2; cc++) {                                        \
            int c16 = l_c0 + cc;                                                \
            size_t ga = (size_t)(bm + l_row0) * 512 + (cch) * 32 + c16 * 8;     \
            size_t gw = (size_t)(bn + l_row0) * 512 + (cch) * 32 + c16 * 8;     \
            uint32_t so = (uint32_t)(l_row0 * LDTB + c16 * 16);                 \
            cp_async16(_sb + so,         Ahi + ga);                             \
            cp_async16(_sb + 10240 + so, Alo + ga);                             \
            cp_async16(_sb + 20480 + so, Whi + gw);                             \
            cp_async16(_sb + 30720 + so, Wlo + gw);                             \
        }                                                                       \
    } while (0)

    GM_LOAD(0, 0); cp_commit();

    for (int c = 0; c < 16; c++) {
        if (c < 15) { GM_LOAD(c + 1, (c + 1) & 1); cp_commit(); cp_wait1(); }
        else cp_wait0();
        __syncthreads();

        const uint32_t ua  = sb0 + (c & 1) * GSTG;
        const uint32_t ual = ua + 10240;
        const uint32_t uwh = ua + 20480;
        const uint32_t uwl = ua + 30720;

#pragma unroll
        for (int ks = 0; ks < 2; ks++) {
            const int kb = ks * 32;
            uint32_t af[4][4];
            uint32_t bh[2][4], bl[2][4];
#pragma unroll
            for (int mf = 0; mf < 4; mf++)
                ldsm_x4(af[mf], ua + (uint32_t)((a_row + mf * 16) * LDTB) + kb + a_colb);
#pragma unroll
            for (int p = 0; p < 2; p++) {
                uint32_t off = (uint32_t)((b_row + p * 16) * LDTB) + kb + b_colb;
                ldsm_x4(bh[p], uwh + off);
                ldsm_x4(bl[p], uwl + off);
            }
#pragma unroll
            for (int mf = 0; mf < 4; mf++)
#pragma unroll
                for (int nf = 0; nf < 4; nf++) {
                    mma16816(acc[mf][nf], af[mf], &bh[nf >> 1][(nf & 1) * 2]);
                    mma16816(acc[mf][nf], af[mf], &bl[nf >> 1][(nf & 1) * 2]);
                }
#pragma unroll
            for (int mf = 0; mf < 4; mf++)
                ldsm_x4(af[mf], ual + (uint32_t)((a_row + mf * 16) * LDTB) + kb + a_colb);
#pragma unroll
            for (int mf = 0; mf < 4; mf++)
#pragma unroll
                for (int nf = 0; nf < 4; nf++)
                    mma16816(acc[mf][nf], af[mf], &bh[nf >> 1][(nf & 1) * 2]);
        }
        __syncthreads();
    }

    // ---- epilogue ----
    const int gid = lane >> 2;
    const int tq  = lane & 3;
#pragma unroll
    for (int mf = 0; mf < 4; mf++) {
#pragma unroll
        for (int nf = 0; nf < 4; nf++) {
            const float* a = acc[mf][nf];
            int m0 = bm + wm + mf * 16 + gid;
            int n0 = bn + wn + nf * 8 + tq * 2;
            float b0 = __ldg(&bias[n0]);
            float b1 = __ldg(&bias[n0 + 1]);
            float v0 = a[0] + b0, v1 = a[1] + b1;
            float v2 = a[2] + b0, v3 = a[3] + b1;
            if (mode == 0) {
                *reinterpret_cast<float2*>(&C[(size_t)m0 * 512 + n0])       = make_float2(v0, v1);
                *reinterpret_cast<float2*>(&C[(size_t)(m0 + 8) * 512 + n0]) = make_float2(v2, v3);
            } else if (mode == 2) {
                split_store(v0, v1, Chi, Clo, (size_t)m0 * 512 + n0);
                split_store(v2, v3, Chi, Clo, (size_t)(m0 + 8) * 512 + n0);
            } else {
                int bi0 = m0 >> 10, l0v = m0 & 1023;
                int m1 = m0 + 8;
                int bi1 = m1 >> 10, l1v = m1 & 1023;
                __nv_bfloat16 h;
                h = __float2bfloat16(v0);
                Chi[((size_t)(bi0*512 + n0    ))*1024 + l0v] = h;
                Clo[((size_t)(bi0*512 + n0    ))*1024 + l0v] = __float2bfloat16(v0 - __bfloat162float(h));
                h = __float2bfloat16(v1);
                Chi[((size_t)(bi0*512 + n0 + 1))*1024 + l0v] = h;
                Clo[((size_t)(bi0*512 + n0 + 1))*1024 + l0v] = __float2bfloat16(v1 - __bfloat162float(h));
                h = __float2bfloat16(v2);
                Chi[((size_t)(bi1*512 + n0    ))*1024 + l1v] = h;
                Clo[((size_t)(bi1*512 + n0    ))*1024 + l1v] = __float2bfloat16(v2 - __bfloat162float(h));
                h = __float2bfloat16(v3);
                Chi[((size_t)(bi1*512 + n0 + 1))*1024 + l1v] = h;
                Clo[((size_t)(bi1*512 + n0 + 1))*1024 + l1v] = __float2bfloat16(v3 - __bfloat162float(h));
            }
        }
    }
}

// ---------------------------------------------------------------------------
// Fused attention, HMMA split-precision QK^T and PV, cp.async double-buffered.
// CTA = (b, h, 32 q rows); 8 warps; S tile 32x1024 fp32 in smem.
// ---------------------------------------------------------------------------
#define SROW 1028
#define AOFF_QHI  131584                       // 32*1028*4
#define AOFF_QLO  (AOFF_QHI + 4608)            // 32*72*2
#define AOFF_K    (AOFF_QLO + 4608)            // 140800
#define KSTG      36864                        // (Kh 18432 + Kl 18432) per stage
#define VSTG      34816                        // (Vh 17408 + Vl 17408) per stage, aliases K
#define AOFF_P    (AOFF_K + 2*KSTG)            // 214528
#define ATTN_SMEM_BYTES (AOFF_P + 17408)       // 231936

__global__ __launch_bounds__(256, 1)
void attn_mma(const __nv_bfloat16* __restrict__ Qhi, const __nv_bfloat16* __restrict__ Qlo,
              const __nv_bfloat16* __restrict__ Khi, const __nv_bfloat16* __restrict__ Klo,
              const __nv_bfloat16* __restrict__ Vthi, const __nv_bfloat16* __restrict__ Vtlo,
              float* __restrict__ scores,
              __nv_bfloat16* __restrict__ mghi, __nv_bfloat16* __restrict__ mglo)
{
    extern __shared__ char smc[];
    float* S = reinterpret_cast<float*>(smc);
    __nv_bfloat16* sQh = reinterpret_cast<__nv_bfloat16*>(smc + AOFF_QHI);
    __nv_bfloat16* sQl = reinterpret_cast<__nv_bfloat16*>(smc + AOFF_QLO);
    __nv_bfloat16* sPh = reinterpret_cast<__nv_bfloat16*>(smc + AOFF_P);
    __nv_bfloat16* sPl = reinterpret_cast<__nv_bfloat16*>(smc + AOFF_P + 8704);

    const uint32_t ub  = smem_u32(smc);
    const uint32_t uQh = ub + AOFF_QHI, uQl = ub + AOFF_QLO;
    const uint32_t uK  = ub + AOFF_K;
    const uint32_t uPh = ub + AOFF_P,   uPl = ub + AOFF_P + 8704;

    const int tid  = threadIdx.x;
    const int lane = tid & 31;
    const int w    = tid >> 5;
    const int qt   = blockIdx.x;
    const int h    = blockIdx.y;
    const int b    = blockIdx.z;
    const int l0   = qt * 32;

    // K-chunk async load: 128 tokens x 64 dims, hi+lo, row stride 144B
#define K_LOAD(jt, stg) do {                                                        \
        uint32_t _kb = uK + (stg) * KSTG;                                           \
        _Pragma("unroll")                                                           \
        for (int i = 0; i < 4; i++) {                                               \
            int idx = tid + i * 256;                                                \
            int r = idx >> 3, c8 = idx & 7;                                         \
            size_t g = ((size_t)(b * 1024 + (jt) * 128 + r)) * 512 + h * 64 + c8 * 8; \
            uint32_t so = (uint32_t)(r * 144 + c8 * 16);                            \
            cp_async16(_kb + so,         Khi + g);                                  \
            cp_async16(_kb + 18432 + so, Klo + g);                                  \
        }                                                                           \
    } while (0)

    // V-chunk async load: 64 dims x 128 tokens, hi+lo, row stride 272B
#define V_LOAD(jt, stg) do {                                                        \
        uint32_t _vb = uK + (stg) * VSTG;                                           \
        _Pragma("unroll")                                                           \
        for (int i = 0; i < 4; i++) {                                               \
            int idx = tid + i * 256;                                                \
            int r = idx >> 4, c = idx & 15;                                         \
            size_t g = ((size_t)(b * 512 + h * 64 + r)) * 1024 + (jt) * 128 + c * 8; \
            uint32_t so = (uint32_t)(r * 272 + c * 16);                             \
            cp_async16(_vb + so,         Vthi + g);                                 \
            cp_async16(_vb + 17408 + so, Vtlo + g);                                 \
        }                                                                           \
    } while (0)

    // prefetch K0 while loading Q
    K_LOAD(0, 0); cp_commit();

    // ---- load Q tile 32x64 hi/lo (stride 72 bf16) ----
    {
        int r = tid >> 3, c = tid & 7;
        size_t g = ((size_t)(b * 1024 + l0 + r)) * 512 + h * 64 + c * 8;
        *reinterpret_cast<uint4*>(&sQh[r * 72 + c * 8]) = *reinterpret_cast<const uint4*>(&Qhi[g]);
        *reinterpret_cast<uint4*>(&sQl[r * 72 + c * 8]) = *reinterpret_cast<const uint4*>(&Qlo[g]);
    }
    __syncthreads();

    const int a_row  = lane & 15;
    const int a_colb = (lane >> 4) * 16;
    const int gid = lane >> 2;
    const int tq  = lane & 3;

    // hoist Q fragments
    uint32_t qh[2][4][4], ql[2][4][4];
#pragma unroll
    for (int mf = 0; mf < 2; mf++)
#pragma unroll
        for (int kk = 0; kk < 4; kk++) {
            uint32_t off = (uint32_t)((mf * 16 + a_row) * 144) + kk * 32 + a_colb;
            ldsm_x4(qh[mf][kk], uQh + off);
            ldsm_x4(ql[mf][kk], uQl + off);
        }

    // ---- S phase: 8 chunks of 128 tokens, double buffered ----
    {
        const int wn = w * 16;
        const int b_row  = wn + ((lane >> 4) << 3) + (lane & 7);
        const int b_colb = ((lane >> 3) & 1) * 16;
        for (int jt = 0; jt < 8; jt++) {
            if (jt < 7) { K_LOAD(jt + 1, (jt + 1) & 1); cp_commit(); cp_wait1(); }
            else cp_wait0();
            __syncthreads();
            const uint32_t uKh = uK + (jt & 1) * KSTG;
            const uint32_t uKl = uKh + 18432;

            float acc[2][2][4];
#pragma unroll
            for (int i = 0; i < 2; i++)
#pragma unroll
                for (int j = 0; j < 2; j++)
#pragma unroll
                    for (int k = 0; k < 4; k++) acc[i][j][k] = 0.0f;

#pragma unroll
            for (int kk = 0; kk < 4; kk++) {
                uint32_t bhf[4], blf[4];
                uint32_t off = (uint32_t)(b_row * 144) + kk * 32 + b_colb;
                ldsm_x4(bhf, uKh + off);
                ldsm_x4(blf, uKl + off);
#pragma unroll
                for (int mf = 0; mf < 2; mf++)
#pragma unroll
                    for (int nf = 0; nf < 2; nf++) {
                        mma16816(acc[mf][nf], qh[mf][kk], &bhf[nf * 2]);
                        mma16816(acc[mf][nf], qh[mf][kk], &blf[nf * 2]);
                        mma16816(acc[mf][nf], ql[mf][kk], &bhf[nf * 2]);
                    }
            }
#pragma unroll
            for (int mf = 0; mf < 2; mf++)
#pragma unroll
                for (int nf = 0; nf < 2; nf++) {
                    int row = mf * 16 + gid;
                    int col = jt * 128 + wn + nf * 8 + tq * 2;
                    const float* a = acc[mf][nf];
                    *reinterpret_cast<float2*>(&S[(size_t)row * SROW + col]) =
                        make_float2(a[0] * 0.125f, a[1] * 0.125f);
                    *reinterpret_cast<float2*>(&S[(size_t)(row + 8) * SROW + col]) =
                        make_float2(a[2] * 0.125f, a[3] * 0.125f);
                }
            __syncthreads();
        }
    }

    // prefetch V0 (aliases K buffers; all K reads done) — overlaps softmax
    V_LOAD(0, 0); cp_commit();

    // ---- softmax per row; write scores once ----
    {
        for (int rr = 0; rr < 4; rr++) {
            int r = w * 4 + rr;
            float* row = &S[(size_t)r * SROW];
            float mx = -1e30f;
            for (int j = lane; j < 1024; j += 32) mx = fmaxf(mx, row[j]);
#pragma unroll
            for (int o = 16; o; o >>= 1) mx = fmaxf(mx, __shfl_xor_sync(0xffffffffu, mx, o));
            float s = 0.0f;
            for (int j = lane; j < 1024; j += 32) {
                float e = __expf(row[j] - mx);
                row[j] = e;
                s += e;
            }
#pragma unroll
            for (int o = 16; o; o >>= 1) s += __shfl_xor_sync(0xffffffffu, s, o);
            float inv = 1.0f / s;
            float* sg = scores + (((size_t)(b * 8 + h)) * 1024 + (l0 + r)) * 1024;
            for (int j = lane; j < 1024; j += 32) {
                float p = row[j] * inv;
                row[j] = p;
                sg[j]  = p;
            }
        }
    }
    __syncthreads();

    // ---- PV phase: 8 chunks, double-buffered V, P re-split per chunk ----
    {
        const int d0 = w * 8;
        float oacc[2][4];
#pragma unroll
        for (int i = 0; i < 2; i++)
#pragma unroll
            for (int j = 0; j < 4; j++) oacc[i][j] = 0.0f;

        const int v_rowb = (d0 + (lane & 7)) * 272;
        const int v_colb = ((lane >> 3) & 1) * 16;

        for (int jt = 0; jt < 8; jt++) {
            if (jt < 7) { V_LOAD(jt + 1, (jt + 1) & 1); cp_commit(); }
            // convert P chunk 32x128 -> Phi/Plo (stride 136 bf16), overlaps V load
#pragma unroll
            for (int i = 0; i < 8; i++) {
                int idx = tid + i * 256;
                int r = idx >> 6, c = (idx & 63) * 2;
                float2 v = *reinterpret_cast<const float2*>(&S[(size_t)r * SROW + jt * 128 + c]);
                __nv_bfloat162 ph, pl;
                ph.x = __float2bfloat16(v.x);
                ph.y = __float2bfloat16(v.y);
                pl.x = __float2bfloat16(v.x - __bfloat162float(ph.x));
                pl.y = __float2bfloat16(v.y - __bfloat162float(ph.y));
                *reinterpret_cast<__nv_bfloat162*>(&sPh[r * 136 + c]) = ph;
                *reinterpret_cast<__nv_bfloat162*>(&sPl[r * 136 + c]) = pl;
            }
            if (jt < 7) cp_wait1(); else cp_wait0();
            __syncthreads();
            const uint32_t uVh = uK + (jt & 1) * VSTG;
            const uint32_t uVl = uVh + 17408;

#pragma unroll
            for (int kk = 0; kk < 8; kk++) {
                uint32_t bh2[2], bl2[2];
                uint32_t voff = (uint32_t)v_rowb + kk * 32 + v_colb;
                ldsm_x2(bh2, uVh + voff);
                ldsm_x2(bl2, uVl + voff);
#pragma unroll
                for (int mf = 0; mf < 2; mf++) {
                    uint32_t ah[4], al[4];
                    uint32_t aoff = (uint32_t)((mf * 16 + a_row) * 272) + kk * 32 + a_colb;
                    ldsm_x4(ah, uPh + aoff);
                    ldsm_x4(al, uPl + aoff);
                    mma16816(oacc[mf], ah, bh2);
                    mma16816(oacc[mf], ah, bl2);
                    mma16816(oacc[mf], al, bh2);
                }
            }
            __syncthreads();
        }

        // epilogue: merged[b, l, d*H + h] as split bf16
#pragma unroll
        for (int mf = 0; mf < 2; mf++) {
            int r0v = mf * 16 + gid;
            int d   = d0 + tq * 2;
            const float* a = oacc[mf];
            size_t base0 = ((size_t)(b * 1024 + l0 + r0v)) * 512 + h;
            size_t base1 = ((size_t)(b * 1024 + l0 + r0v + 8)) * 512 + h;
            __nv_bfloat16 hh;
            hh = __float2bfloat16(a[0]);
            mghi[base0 + (size_t)d * 8]       = hh;
            mglo[base0 + (size_t)d * 8]       = __float2bfloat16(a[0] - __bfloat162float(hh));
            hh = __float2bfloat16(a[1]);
            mghi[base0 + (size_t)(d + 1) * 8] = hh;
            mglo[base0 + (size_t)(d + 1) * 8] = __float2bfloat16(a[1] - __bfloat162float(hh));
            hh = __float2bfloat16(a[2]);
            mghi[base1 + (size_t)d * 8]       = hh;
            mglo[base1 + (size_t)d * 8]       = __float2bfloat16(a[2] - __bfloat162float(hh));
            hh = __float2bfloat16(a[3]);
            mghi[base1 + (size_t)(d + 1) * 8] = hh;
            mglo[base1 + (size_t)(d + 1) * 8] = __float2bfloat16(a[3] - __bfloat162float(hh));
        }
    }
}

// ---------------------------------------------------------------------------
// Launch
// ---------------------------------------------------------------------------
extern "C" void kernel_launch(void* const* d_in, const int* in_sizes, int n_in,
                              void* d_out, int out_size)
{
    const float* x  = (const float*)d_in[0];
    const float* Wc = (const float*)d_in[1];
    const float* bc = (const float*)d_in[2];
    const float* Wq = (const float*)d_in[3];
    const float* bq = (const float*)d_in[4];
    const float* Wk = (const float*)d_in[5];
    const float* bk = (const float*)d_in[6];
    const float* Wv = (const float*)d_in[7];
    const float* bv = (const float*)d_in[8];
    const float* Wo = (const float*)d_in[9];
    const float* bo = (const float*)d_in[10];

    float* out    = (float*)d_out;
    float* scores = out + (size_t)Bb * Ll * Dd;

    __nv_bfloat16 *xhi, *xlo, *xrhi, *xrlo, *qhi, *qlo, *khi, *klo,
                  *vthi, *vtlo, *mghi, *mglo, *whi, *wlo;
    cudaGetSymbolAddress((void**)&xhi,  g_xhi);
    cudaGetSymbolAddress((void**)&xlo,  g_xlo);
    cudaGetSymbolAddress((void**)&xrhi, g_xrhi);
    cudaGetSymbolAddress((void**)&xrlo, g_xrlo);
    cudaGetSymbolAddress((void**)&qhi,  g_Qhi);
    cudaGetSymbolAddress((void**)&qlo,  g_Qlo);
    cudaGetSymbolAddress((void**)&khi,  g_Khi);
    cudaGetSymbolAddress((void**)&klo,  g_Klo);
    cudaGetSymbolAddress((void**)&vthi, g_Vthi);
    cudaGetSymbolAddress((void**)&vtlo, g_Vtlo);
    cudaGetSymbolAddress((void**)&mghi, g_mghi);
    cudaGetSymbolAddress((void**)&mglo, g_mglo);
    cudaGetSymbolAddress((void**)&whi,  g_whi);
    cudaGetSymbolAddress((void**)&wlo,  g_wlo);

    cudaFuncSetAttribute((const void*)attn_mma,
                         cudaFuncAttributeMaxDynamicSharedMemorySize, ATTN_SMEM_BYTES);
    cudaFuncSetAttribute((const void*)tg_gemm,
                         cudaFuncAttributeMaxDynamicSharedMemorySize, GM_SMEM);

    const int WN = Dd * Dd;
    cvt_split<<<(Mrows*Dd/4 + 255)/256, 256>>>(x, xhi, xlo, Mrows*Dd/4);
    cvt_split5<<<dim3(WN/4/256, 5), 256>>>(Wc, Wq, Wk, Wv, Wo, whi, wlo);

    dim3 gg(Mrows / 128, Dd / 128);   // (64, 4)

    // x_r = x @ Wc^T + bc  (split bf16 row-major)
    tg_gemm<<<gg, 256, GM_SMEM>>>(xhi, xlo, whi + 0*WN, wlo + 0*WN, bc,
                                  nullptr, xrhi, xrlo, 2);
    // Q = x @ Wq^T + bq    (split bf16 row-major)
    tg_gemm<<<gg, 256, GM_SMEM>>>(xhi, xlo, whi + 1*WN, wlo + 1*WN, bq,
                                  nullptr, qhi, qlo, 2);
    // K = x_r @ Wk^T + bk  (split bf16 row-major)
    tg_gemm<<<gg, 256, GM_SMEM>>>(xrhi, xrlo, whi + 2*WN, wlo + 2*WN, bk,
                                  nullptr, khi, klo, 2);
    // V = x_r @ Wv^T + bv  (split bf16 transposed Vt)
    tg_gemm<<<gg, 256, GM_SMEM>>>(xrhi, xrlo, whi + 3*WN, wlo + 3*WN, bv,
                                  nullptr, vthi, vtlo, 3);

    attn_mma<<<dim3(32, Hh, Bb), 256, ATTN_SMEM_BYTES>>>(
        qhi, qlo, khi, klo, vthi, vtlo, scores, mghi, mglo);

    // out = merged @ Wo^T + bo  (fp32)
    tg_gemm<<<gg, 256, GM_SMEM>>>(mghi, mglo, whi + 4*WN, wlo + 4*WN, bo,
                                  out, nullptr, nullptr, 0);
}

// round 16
// speedup vs baseline: 1.8320x; 1.0149x over previous
#include <cuda_runtime.h>
#include <cuda_bf16.h>
#include <cstdint>
#include <cstddef>

// Problem constants
#define Bb   8
#define Ll   1024
#define Dd   512
#define Hh   8
#define Qd   64
#define Mrows (Bb*Ll)          // 8192

// ---------------------------------------------------------------------------
// Scratch (no cudaMalloc allowed)
// ---------------------------------------------------------------------------
__device__ __nv_bfloat16 g_xhi [Mrows*Dd];
__device__ __nv_bfloat16 g_xlo [Mrows*Dd];
__device__ __nv_bfloat16 g_xrhi[Mrows*Dd];
__device__ __nv_bfloat16 g_xrlo[Mrows*Dd];
__device__ __nv_bfloat16 g_Qhi [Mrows*Dd];
__device__ __nv_bfloat16 g_Qlo [Mrows*Dd];
__device__ __nv_bfloat16 g_Khi [Mrows*Dd];
__device__ __nv_bfloat16 g_Klo [Mrows*Dd];
__device__ __nv_bfloat16 g_Vthi[Mrows*Dd];  // Vt[(b*512 + h*64 + d)*1024 + l]
__device__ __nv_bfloat16 g_Vtlo[Mrows*Dd];
__device__ __nv_bfloat16 g_mghi[Mrows*Dd];  // merged[b,l, d*H + h]
__device__ __nv_bfloat16 g_mglo[Mrows*Dd];
__device__ __nv_bfloat16 g_whi [5*Dd*Dd];   // Wc,Wq,Wk,Wv,Wo
__device__ __nv_bfloat16 g_wlo [5*Dd*Dd];

// ---------------------------------------------------------------------------
// PTX helpers
// ---------------------------------------------------------------------------
__device__ __forceinline__ uint32_t smem_u32(const void* p) {
    uint32_t a;
    asm("{ .reg .u64 t; cvta.to.shared.u64 t, %1; cvt.u32.u64 %0, t; }" : "=r"(a) : "l"(p));
    return a;
}
__device__ __forceinline__ void ldsm_x4(uint32_t* r, uint32_t addr) {
    asm volatile("ldmatrix.sync.aligned.m8n8.x4.shared.b16 {%0,%1,%2,%3}, [%4];"
        : "=r"(r[0]), "=r"(r[1]), "=r"(r[2]), "=r"(r[3]) : "r"(addr));
}
__device__ __forceinline__ void mma16816(float* c, const uint32_t* a, const uint32_t* b) {
    asm volatile("mma.sync.aligned.m16n8k16.row.col.f32.bf16.bf16.f32 "
        "{%0,%1,%2,%3}, {%4,%5,%6,%7}, {%8,%9}, {%0,%1,%2,%3};"
        : "+f"(c[0]), "+f"(c[1]), "+f"(c[2]), "+f"(c[3])
        : "r"(a[0]), "r"(a[1]), "r"(a[2]), "r"(a[3]), "r"(b[0]), "r"(b[1]));
}
__device__ __forceinline__ void cp_async16(uint32_t s, const void* g) {
    asm volatile("cp.async.cg.shared.global [%0], [%1], 16;" :: "r"(s), "l"(g));
}
__device__ __forceinline__ void cp_commit() { asm volatile("cp.async.commit_group;" ::: "memory"); }
__device__ __forceinline__ void cp_wait0()  { asm volatile("cp.async.wait_group 0;" ::: "memory"); }

// ---------------------------------------------------------------------------
// fp32 -> bf16 hi/lo split helpers
// ---------------------------------------------------------------------------
__device__ __forceinline__ void split_store(float vx, float vy,
                                            __nv_bfloat16* hi, __nv_bfloat16* lo, size_t idx)
{
    __nv_bfloat162 ph, pl;
    ph.x = __float2bfloat16(vx); ph.y = __float2bfloat16(vy);
    pl.x = __float2bfloat16(vx - __bfloat162float(ph.x));
    pl.y = __float2bfloat16(vy - __bfloat162float(ph.y));
    *reinterpret_cast<__nv_bfloat162*>(hi + idx) = ph;
    *reinterpret_cast<__nv_bfloat162*>(lo + idx) = pl;
}
// pack float2 -> bf16x2 hi & lo fragments (same rounding as split_store)
__device__ __forceinline__ void split_pack(float2 v, uint32_t& h, uint32_t& l) {
    __nv_bfloat162 hh;
    hh.x = __float2bfloat16(v.x); hh.y = __float2bfloat16(v.y);
    __nv_bfloat162 ll;
    ll.x = __float2bfloat16(v.x - __bfloat162float(hh.x));
    ll.y = __float2bfloat16(v.y - __bfloat162float(hh.y));
    h = *reinterpret_cast<uint32_t*>(&hh);
    l = *reinterpret_cast<uint32_t*>(&ll);
}

__global__ void cvt_split(const float* __restrict__ in,
                          __nv_bfloat16* __restrict__ hi,
                          __nv_bfloat16* __restrict__ lo, int n4)
{
    int i = blockIdx.x * blockDim.x + threadIdx.x;
    if (i >= n4) return;
    float4 v = reinterpret_cast<const float4*>(in)[i];
    split_store(v.x, v.y, hi, lo, (size_t)i * 4);
    split_store(v.z, v.w, hi, lo, (size_t)i * 4 + 2);
}

__global__ void cvt_split5(const float* __restrict__ w0, const float* __restrict__ w1,
                           const float* __restrict__ w2, const float* __restrict__ w3,
                           const float* __restrict__ w4,
                           __nv_bfloat16* __restrict__ hi, __nv_bfloat16* __restrict__ lo)
{
    const int seg = blockIdx.y;
    const float* in = (seg == 0) ? w0 : (seg == 1) ? w1 : (seg == 2) ? w2 : (seg == 3) ? w3 : w4;
    hi += (size_t)seg * Dd * Dd;
    lo += (size_t)seg * Dd * Dd;
    int i = blockIdx.x * blockDim.x + threadIdx.x;
    float4 v = reinterpret_cast<const float4*>(in)[i];
    split_store(v.x, v.y, hi, lo, (size_t)i * 4);
    split_store(v.z, v.w, hi, lo, (size_t)i * 4 + 2);
}

// ---------------------------------------------------------------------------
// HMMA split-precision GEMM, cp.async double-buffered (1 sync per chunk).
// ---------------------------------------------------------------------------
#define LDTB 80
#define GSTG 40960
#define GM_SMEM (2*GSTG)

__global__ __launch_bounds__(256, 2)
void tg_gemm(const __nv_bfloat16* __restrict__ Ahi, const __nv_bfloat16* __restrict__ Alo,
             const __nv_bfloat16* __restrict__ Whi, const __nv_bfloat16* __restrict__ Wlo,
             const float* __restrict__ bias, float* __restrict__ C,
             __nv_bfloat16* __restrict__ Chi, __nv_bfloat16* __restrict__ Clo,
             int mode)
{
    extern __shared__ char gsm[];
    const uint32_t sb0 = smem_u32(gsm);

    const int tid  = threadIdx.x;
    const int wid  = tid >> 5;
    const int lane = tid & 31;
    const int bm   = blockIdx.x * 128;
    const int bn   = blockIdx.y * 128;
    const int wm = (wid >> 2) * 64;
    const int wn = (wid & 3) * 32;

    float acc[4][4][4];
#pragma unroll
    for (int i = 0; i < 4; i++)
#pragma unroll
        for (int j = 0; j < 4; j++)
#pragma unroll
            for (int k = 0; k < 4; k++) acc[i][j][k] = 0.0f;

    const int a_row  = wm + (lane & 15);
    const int a_colb = (lane >> 4) * 16;
    const int b_row  = wn + ((lane >> 4) << 3) + (lane & 7);
    const int b_colb = ((lane >> 3) & 1) * 16;

    const int l_row0 = tid >> 1;
    const int l_c0   = (tid & 1) * 2;

#define GM_LOAD(cch, stg) do {                                                  \
        uint32_t _sb = sb0 + (stg) * GSTG;                                      \
        _Pragma("unroll")                                                       \
        for (int cc = 0; cc < 2; cc++) {                                        \
            int c16 = l_c0 + cc;                                                \
            size_t ga = (size_t)(bm + l_row0) * 512 + (cch) * 32 + c16 * 8;     \
            size_t gw = (size_t)(bn + l_row0) * 512 + (cch) * 32 + c16 * 8;     \
            uint32_t so = (uint32_t)(l_row0 * LDTB + c16 * 16);                 \
            cp_async16(_sb + so,         Ahi + ga);                             \
            cp_async16(_sb + 10240 + so, Alo + ga);                             \
            cp_async16(_sb + 20480 + so, Whi + gw);                             \
            cp_async16(_sb + 30720 + so, Wlo + gw);                             \
        }                                                                       \
    } while (0)

    GM_LOAD(0, 0); cp_commit();

    for (int c = 0; c < 16; c++) {
        cp_wait0();
        __syncthreads();
        if (c < 15) { GM_LOAD(c + 1, (c + 1) & 1); cp_commit(); }

        const uint32_t ua  = sb0 + (c & 1) * GSTG;
        const uint32_t ual = ua + 10240;
        const uint32_t uwh = ua + 20480;
        const uint32_t uwl = ua + 30720;

#pragma unroll
        for (int ks = 0; ks < 2; ks++) {
            const int kb = ks * 32;
            uint32_t af[4][4];
            uint32_t bh[2][4], bl[2][4];
#pragma unroll
            for (int mf = 0; mf < 4; mf++)
                ldsm_x4(af[mf], ua + (uint32_t)((a_row + mf * 16) * LDTB) + kb + a_colb);
#pragma unroll
            for (int p = 0; p < 2; p++) {
                uint32_t off = (uint32_t)((b_row + p * 16) * LDTB) + kb + b_colb;
                ldsm_x4(bh[p], uwh + off);
                ldsm_x4(bl[p], uwl + off);
            }
#pragma unroll
            for (int mf = 0; mf < 4; mf++)
#pragma unroll
                for (int nf = 0; nf < 4; nf++) {
                    mma16816(acc[mf][nf], af[mf], &bh[nf >> 1][(nf & 1) * 2]);
                    mma16816(acc[mf][nf], af[mf], &bl[nf >> 1][(nf & 1) * 2]);
                }
#pragma unroll
            for (int mf = 0; mf < 4; mf++)
                ldsm_x4(af[mf], ual + (uint32_t)((a_row + mf * 16) * LDTB) + kb + a_colb);
#pragma unroll
            for (int mf = 0; mf < 4; mf++)
#pragma unroll
                for (int nf = 0; nf < 4; nf++)
                    mma16816(acc[mf][nf], af[mf], &bh[nf >> 1][(nf & 1) * 2]);
        }
    }

    // ---- epilogue ----
    const int gid = lane >> 2;
    const int tq  = lane & 3;
#pragma unroll
    for (int mf = 0; mf < 4; mf++) {
#pragma unroll
        for (int nf = 0; nf < 4; nf++) {
            const float* a = acc[mf][nf];
            int m0 = bm + wm + mf * 16 + gid;
            int n0 = bn + wn + nf * 8 + tq * 2;
            float b0 = __ldg(&bias[n0]);
            float b1 = __ldg(&bias[n0 + 1]);
            float v0 = a[0] + b0, v1 = a[1] + b1;
            float v2 = a[2] + b0, v3 = a[3] + b1;
            if (mode == 0) {
                *reinterpret_cast<float2*>(&C[(size_t)m0 * 512 + n0])       = make_float2(v0, v1);
                *reinterpret_cast<float2*>(&C[(size_t)(m0 + 8) * 512 + n0]) = make_float2(v2, v3);
            } else if (mode == 2) {
                split_store(v0, v1, Chi, Clo, (size_t)m0 * 512 + n0);
                split_store(v2, v3, Chi, Clo, (size_t)(m0 + 8) * 512 + n0);
            } else {
                int bi0 = m0 >> 10, l0v = m0 & 1023;
                int m1 = m0 + 8;
                int bi1 = m1 >> 10, l1v = m1 & 1023;
                __nv_bfloat16 h;
                h = __float2bfloat16(v0);
                Chi[((size_t)(bi0*512 + n0    ))*1024 + l0v] = h;
                Clo[((size_t)(bi0*512 + n0    ))*1024 + l0v] = __float2bfloat16(v0 - __bfloat162float(h));
                h = __float2bfloat16(v1);
                Chi[((size_t)(bi0*512 + n0 + 1))*1024 + l0v] = h;
                Clo[((size_t)(bi0*512 + n0 + 1))*1024 + l0v] = __float2bfloat16(v1 - __bfloat162float(h));
                h = __float2bfloat16(v2);
                Chi[((size_t)(bi1*512 + n0    ))*1024 + l1v] = h;
                Clo[((size_t)(bi1*512 + n0    ))*1024 + l1v] = __float2bfloat16(v2 - __bfloat162float(h));
                h = __float2bfloat16(v3);
                Chi[((size_t)(bi1*512 + n0 + 1))*1024 + l1v] = h;
                Clo[((size_t)(bi1*512 + n0 + 1))*1024 + l1v] = __float2bfloat16(v3 - __bfloat162float(h));
            }
        }
    }
}

// ---------------------------------------------------------------------------
// Fused attention: HMMA split QK^T and PV; P fragments built directly from
// fp32 S in registers (no P smem); 1 sync per pipelined chunk.
// ---------------------------------------------------------------------------
#define SROW 1028
#define AOFF_QHI  131584                       // 32*1028*4
#define AOFF_QLO  (AOFF_QHI + 4608)
#define AOFF_K    (AOFF_QLO + 4608)            // 140800
#define KSTG      36864
#define VSTG      34816
#define ATTN_SMEM_BYTES (AOFF_K + 2*KSTG)      // 214528

__global__ __launch_bounds__(256, 1)
void attn_mma(const __nv_bfloat16* __restrict__ Qhi, const __nv_bfloat16* __restrict__ Qlo,
              const __nv_bfloat16* __restrict__ Khi, const __nv_bfloat16* __restrict__ Klo,
              const __nv_bfloat16* __restrict__ Vthi, const __nv_bfloat16* __restrict__ Vtlo,
              float* __restrict__ scores,
              __nv_bfloat16* __restrict__ mghi, __nv_bfloat16* __restrict__ mglo)
{
    extern __shared__ char smc[];
    float* S = reinterpret_cast<float*>(smc);
    __nv_bfloat16* sQh = reinterpret_cast<__nv_bfloat16*>(smc + AOFF_QHI);
    __nv_bfloat16* sQl = reinterpret_cast<__nv_bfloat16*>(smc + AOFF_QLO);

    const uint32_t ub  = smem_u32(smc);
    const uint32_t uQh = ub + AOFF_QHI, uQl = ub + AOFF_QLO;
    const uint32_t uK  = ub + AOFF_K;

    const int tid  = threadIdx.x;
    const int lane = tid & 31;
    const int w    = tid >> 5;
    const int qt   = blockIdx.x;
    const int h    = blockIdx.y;
    const int b    = blockIdx.z;
    const int l0   = qt * 32;

#define K_LOAD(jt, stg) do {                                                        \
        uint32_t _kb = uK + (stg) * KSTG;                                           \
        _Pragma("unroll")                                                           \
        for (int i = 0; i < 4; i++) {                                               \
            int idx = tid + i * 256;                                                \
            int r = idx >> 3, c8 = idx & 7;                                         \
            size_t g = ((size_t)(b * 1024 + (jt) * 128 + r)) * 512 + h * 64 + c8 * 8; \
            uint32_t so = (uint32_t)(r * 144 + c8 * 16);                            \
            cp_async16(_kb + so,         Khi + g);                                  \
            cp_async16(_kb + 18432 + so, Klo + g);                                  \
        }                                                                           \
    } while (0)

#define V_LOAD(jt, stg) do {                                                        \
        uint32_t _vb = uK + (stg) * VSTG;                                           \
        _Pragma("unroll")                                                           \
        for (int i = 0; i < 4; i++) {                                               \
            int idx = tid + i * 256;                                                \
            int r = idx >> 4, c = idx & 15;                                         \
            size_t g = ((size_t)(b * 512 + h * 64 + r)) * 1024 + (jt) * 128 + c * 8; \
            uint32_t so = (uint32_t)(r * 272 + c * 16);                             \
            cp_async16(_vb + so,         Vthi + g);                                 \
            cp_async16(_vb + 17408 + so, Vtlo + g);                                 \
        }                                                                           \
    } while (0)

    // prefetch K0 while loading Q
    K_LOAD(0, 0); cp_commit();

    {
        int r = tid >> 3, c = tid & 7;
        size_t g = ((size_t)(b * 1024 + l0 + r)) * 512 + h * 64 + c * 8;
        *reinterpret_cast<uint4*>(&sQh[r * 72 + c * 8]) = *reinterpret_cast<const uint4*>(&Qhi[g]);
        *reinterpret_cast<uint4*>(&sQl[r * 72 + c * 8]) = *reinterpret_cast<const uint4*>(&Qlo[g]);
    }
    __syncthreads();

    const int a_row  = lane & 15;
    const int a_colb = (lane >> 4) * 16;
    const int gid = lane >> 2;
    const int tq  = lane & 3;

    // hoist Q fragments
    uint32_t qh[2][4][4], ql[2][4][4];
#pragma unroll
    for (int mf = 0; mf < 2; mf++)
#pragma unroll
        for (int kk = 0; kk < 4; kk++) {
            uint32_t off = (uint32_t)((mf * 16 + a_row) * 144) + kk * 32 + a_colb;
            ldsm_x4(qh[mf][kk], uQh + off);
            ldsm_x4(ql[mf][kk], uQl + off);
        }

    // ---- S phase: 8 chunks of 128 tokens, 1 sync per chunk ----
    {
        const int wn = w * 16;
        const int b_row  = wn + ((lane >> 4) << 3) + (lane & 7);
        const int b_colb = ((lane >> 3) & 1) * 16;
        for (int jt = 0; jt < 8; jt++) {
            cp_wait0();
            __syncthreads();
            if (jt < 7) { K_LOAD(jt + 1, (jt + 1) & 1); cp_commit(); }
            const uint32_t uKh = uK + (jt & 1) * KSTG;
            const uint32_t uKl = uKh + 18432;

            float acc[2][2][4];
#pragma unroll
            for (int i = 0; i < 2; i++)
#pragma unroll
                for (int j = 0; j < 2; j++)
#pragma unroll
                    for (int k = 0; k < 4; k++) acc[i][j][k] = 0.0f;

#pragma unroll
            for (int kk = 0; kk < 4; kk++) {
                uint32_t bhf[4], blf[4];
                uint32_t off = (uint32_t)(b_row * 144) + kk * 32 + b_colb;
                ldsm_x4(bhf, uKh + off);
                ldsm_x4(blf, uKl + off);
#pragma unroll
                for (int mf = 0; mf < 2; mf++)
#pragma unroll
                    for (int nf = 0; nf < 2; nf++) {
                        mma16816(acc[mf][nf], qh[mf][kk], &bhf[nf * 2]);
                        mma16816(acc[mf][nf], qh[mf][kk], &blf[nf * 2]);
                        mma16816(acc[mf][nf], ql[mf][kk], &bhf[nf * 2]);
                    }
            }
#pragma unroll
            for (int mf = 0; mf < 2; mf++)
#pragma unroll
                for (int nf = 0; nf < 2; nf++) {
                    int row = mf * 16 + gid;
                    int col = jt * 128 + wn + nf * 8 + tq * 2;
                    const float* a = acc[mf][nf];
                    *reinterpret_cast<float2*>(&S[(size_t)row * SROW + col]) =
                        make_float2(a[0] * 0.125f, a[1] * 0.125f);
                    *reinterpret_cast<float2*>(&S[(size_t)(row + 8) * SROW + col]) =
                        make_float2(a[2] * 0.125f, a[3] * 0.125f);
                }
        }
    }

    // prefetch V0 (aliases K stage0; safe: all warps past last S sync read stage1)
    V_LOAD(0, 0); cp_commit();
    __syncthreads();   // S complete for softmax

    // ---- softmax per row; write scores once ----
    {
        for (int rr = 0; rr < 4; rr++) {
            int r = w * 4 + rr;
            float* row = &S[(size_t)r * SROW];
            float mx = -1e30f;
            for (int j = lane; j < 1024; j += 32) mx = fmaxf(mx, row[j]);
#pragma unroll
            for (int o = 16; o; o >>= 1) mx = fmaxf(mx, __shfl_xor_sync(0xffffffffu, mx, o));
            float s = 0.0f;
            for (int j = lane; j < 1024; j += 32) {
                float e = __expf(row[j] - mx);
                row[j] = e;
                s += e;
            }
#pragma unroll
            for (int o = 16; o; o >>= 1) s += __shfl_xor_sync(0xffffffffu, s, o);
            float inv = 1.0f / s;
            float* sg = scores + (((size_t)(b * 8 + h)) * 1024 + (l0 + r)) * 1024;
            for (int j = lane; j < 1024; j += 32) {
                float p = row[j] * inv;
                row[j] = p;
                sg[j]  = p;
            }
        }
    }
    __syncthreads();   // all P visible before PV reads S cross-warp

    // ---- PV phase: warp = 16 rows x 16 dims; P frags built from S in regs ----
    {
        const int wr = w >> 2;          // 0..1 : row group (16 rows)
        const int wd = w & 3;           // 0..3 : dim group (16 dims)
        float acc[2][4];
#pragma unroll
        for (int i = 0; i < 2; i++)
#pragma unroll
            for (int j = 0; j < 4; j++) acc[i][j] = 0.0f;

        const int vrow = (wd * 16 + (lane & 7)) * 272;
        const int vsel = ((lane >> 3) & 3) * 16;
        const int r0   = wr * 16 + gid;

        for (int jt = 0; jt < 8; jt++) {
            cp_wait0();
            __syncthreads();
            if (jt < 7) { V_LOAD(jt + 1, (jt + 1) & 1); cp_commit(); }
            const uint32_t uVh = uK + (jt & 1) * VSTG;
            const uint32_t uVl = uVh + 17408;

#pragma unroll
            for (int kp = 0; kp < 4; kp++) {
                uint32_t vh[2][4], vl[2][4];
#pragma unroll
                for (int nf = 0; nf < 2; nf++) {
                    uint32_t off = (uint32_t)(vrow + nf * 8 * 272 + kp * 64 + vsel);
                    ldsm_x4(vh[nf], uVh + off);
                    ldsm_x4(vl[nf], uVl + off);
                }
#pragma unroll
                for (int k2 = 0; k2 < 2; k2++) {
                    const int cb = jt * 128 + (kp * 2 + k2) * 16 + tq * 2;
                    float2 s00 = *reinterpret_cast<const float2*>(&S[(size_t)r0 * SROW + cb]);
                    float2 s10 = *reinterpret_cast<const float2*>(&S[(size_t)(r0 + 8) * SROW + cb]);
                    float2 s01 = *reinterpret_cast<const float2*>(&S[(size_t)r0 * SROW + cb + 8]);
                    float2 s11 = *reinterpret_cast<const float2*>(&S[(size_t)(r0 + 8) * SROW + cb + 8]);
                    uint32_t ah[4], al[4];
                    split_pack(s00, ah[0], al[0]);
                    split_pack(s10, ah[1], al[1]);
                    split_pack(s01, ah[2], al[2]);
                    split_pack(s11, ah[3], al[3]);
#pragma unroll
                    for (int nf = 0; nf < 2; nf++) {
                        mma16816(acc[nf], ah, &vh[nf][k2 * 2]);
                        mma16816(acc[nf], ah, &vl[nf][k2 * 2]);
                        mma16816(acc[nf], al, &vh[nf][k2 * 2]);
                    }
                }
            }
        }

        // epilogue: merged[b, l, d*H + h] as split bf16
#pragma unroll
        for (int nf = 0; nf < 2; nf++) {
            const float* a = acc[nf];
            int row = l0 + wr * 16 + gid;
            int d   = wd * 16 + nf * 8 + tq * 2;
            size_t base0 = ((size_t)(b * 1024 + row)) * 512 + h;
            size_t base1 = ((size_t)(b * 1024 + row + 8)) * 512 + h;
            __nv_bfloat16 hh;
            hh = __float2bfloat16(a[0]);
            mghi[base0 + (size_t)d * 8]       = hh;
            mglo[base0 + (size_t)d * 8]       = __float2bfloat16(a[0] - __bfloat162float(hh));
            hh = __float2bfloat16(a[1]);
            mghi[base0 + (size_t)(d + 1) * 8] = hh;
            mglo[base0 + (size_t)(d + 1) * 8] = __float2bfloat16(a[1] - __bfloat162float(hh));
            hh = __float2bfloat16(a[2]);
            mghi[base1 + (size_t)d * 8]       = hh;
            mglo[base1 + (size_t)d * 8]       = __float2bfloat16(a[2] - __bfloat162float(hh));
            hh = __float2bfloat16(a[3]);
            mghi[base1 + (size_t)(d + 1) * 8] = hh;
            mglo[base1 + (size_t)(d + 1) * 8] = __float2bfloat16(a[3] - __bfloat162float(hh));
        }
    }
}

// ---------------------------------------------------------------------------
// Launch
// ---------------------------------------------------------------------------
extern "C" void kernel_launch(void* const* d_in, const int* in_sizes, int n_in,
                              void* d_out, int out_size)
{
    const float* x  = (const float*)d_in[0];
    const float* Wc = (const float*)d_in[1];
    const float* bc = (const float*)d_in[2];
    const float* Wq = (const float*)d_in[3];
    const float* bq = (const float*)d_in[4];
    const float* Wk = (const float*)d_in[5];
    const float* bk = (const float*)d_in[6];
    const float* Wv = (const float*)d_in[7];
    const float* bv = (const float*)d_in[8];
    const float* Wo = (const float*)d_in[9];
    const float* bo = (const float*)d_in[10];

    float* out    = (float*)d_out;
    float* scores = out + (size_t)Bb * Ll * Dd;

    __nv_bfloat16 *xhi, *xlo, *xrhi, *xrlo, *qhi, *qlo, *khi, *klo,
                  *vthi, *vtlo, *mghi, *mglo, *whi, *wlo;
    cudaGetSymbolAddress((void**)&xhi,  g_xhi);
    cudaGetSymbolAddress((void**)&xlo,  g_xlo);
    cudaGetSymbolAddress((void**)&xrhi, g_xrhi);
    cudaGetSymbolAddress((void**)&xrlo, g_xrlo);
    cudaGetSymbolAddress((void**)&qhi,  g_Qhi);
    cudaGetSymbolAddress((void**)&qlo,  g_Qlo);
    cudaGetSymbolAddress((void**)&khi,  g_Khi);
    cudaGetSymbolAddress((void**)&klo,  g_Klo);
    cudaGetSymbolAddress((void**)&vthi, g_Vthi);
    cudaGetSymbolAddress((void**)&vtlo, g_Vtlo);
    cudaGetSymbolAddress((void**)&mghi, g_mghi);
    cudaGetSymbolAddress((void**)&mglo, g_mglo);
    cudaGetSymbolAddress((void**)&whi,  g_whi);
    cudaGetSymbolAddress((void**)&wlo,  g_wlo);

    cudaFuncSetAttribute((const void*)attn_mma,
                         cudaFuncAttributeMaxDynamicSharedMemorySize, ATTN_SMEM_BYTES);
    cudaFuncSetAttribute((const void*)tg_gemm,
                         cudaFuncAttributeMaxDynamicSharedMemorySize, GM_SMEM);

    const int WN = Dd * Dd;
    cvt_split<<<(Mrows*Dd/4 + 255)/256, 256>>>(x, xhi, xlo, Mrows*Dd/4);
    cvt_split5<<<dim3(WN/4/256, 5), 256>>>(Wc, Wq, Wk, Wv, Wo, whi, wlo);

    dim3 gg(Mrows / 128, Dd / 128);   // (64, 4)

    tg_gemm<<<gg, 256, GM_SMEM>>>(xhi, xlo, whi + 0*WN, wlo + 0*WN, bc,
                                  nullptr, xrhi, xrlo, 2);
    tg_gemm<<<gg, 256, GM_SMEM>>>(xhi, xlo, whi + 1*WN, wlo + 1*WN, bq,
                                  nullptr, qhi, qlo, 2);
    tg_gemm<<<gg, 256, GM_SMEM>>>(xrhi, xrlo, whi + 2*WN, wlo + 2*WN, bk,
                                  nullptr, khi, klo, 2);
    tg_gemm<<<gg, 256, GM_SMEM>>>(xrhi, xrlo, whi + 3*WN, wlo + 3*WN, bv,
                                  nullptr, vthi, vtlo, 3);

    attn_mma<<<dim3(32, Hh, Bb), 256, ATTN_SMEM_BYTES>>>(
        qhi, qlo, khi, klo, vthi, vtlo, scores, mghi, mglo);

    tg_gemm<<<gg, 256, GM_SMEM>>>(mghi, mglo, whi + 4*WN, wlo + 4*WN, bo,
                                  out, nullptr, nullptr, 0);
}